// round 5
// baseline (speedup 1.0000x reference)
#include <cuda_runtime.h>
#include <cstdint>

#define BATCH 8
#define LSEQ  1024
#define DM    256
#define DS    16
#define DC    4
#define DI    512
#define DTR   16
#define BL    (BATCH * LSEQ)   // 8192
#define XDBLC (DTR + 2 * DS)   // 48
#define CH    128
#define NCH   (LSEQ / CH)      // 8

// ---------------- scratch (single static device buffer; no allocations) ---
static const size_t OFF_XN    = 0;
static const size_t OFF_XR    = OFF_XN    + (size_t)BL * DM;
static const size_t OFF_XSC   = OFF_XR    + (size_t)2 * BL * 2 * DI;
static const size_t OFF_XDBL  = OFF_XSC   + (size_t)2 * BL * DI;
static const size_t OFF_DELTA = OFF_XDBL  + (size_t)2 * BL * XDBLC;
static const size_t OFF_Y     = OFF_DELTA + (size_t)2 * BL * DI;
static const size_t OFF_WC    = OFF_Y     + (size_t)2 * BL * DI;     // combined weights 1024x256
static const size_t OFF_HF    = OFF_WC    + (size_t)1024 * 256;
static const size_t OFF_DS    = OFF_HF    + (size_t)2 * 8 * NCH * 16 * 512;
static const size_t TOTAL_F   = OFF_DS    + (size_t)2 * 8 * NCH * 512;

__device__ float g_buf[TOTAL_F];

// ---------------- LayerNorm ------------------------------------------------
__global__ void ln_kernel(const float* __restrict__ x,
                          const float* __restrict__ g,
                          const float* __restrict__ b,
                          float* __restrict__ xn)
{
    int m = blockIdx.x;
    int t = threadIdx.x;
    float v = x[(size_t)m * DM + t];
    float s = v, s2 = v * v;
    #pragma unroll
    for (int o = 16; o; o >>= 1) {
        s  += __shfl_xor_sync(0xffffffffu, s,  o);
        s2 += __shfl_xor_sync(0xffffffffu, s2, o);
    }
    __shared__ float ws[8], ws2[8];
    int w = t >> 5, l = t & 31;
    if (l == 0) { ws[w] = s; ws2[w] = s2; }
    __syncthreads();
    float S = 0.f, S2 = 0.f;
    #pragma unroll
    for (int i = 0; i < 8; i++) { S += ws[i]; S2 += ws2[i]; }
    float mu  = S * (1.0f / DM);
    float var = S2 * (1.0f / DM) - mu * mu;
    float r = rsqrtf(var + 1e-5f);
    xn[(size_t)m * DM + t] = (v - mu) * r * g[t] + b[t];
}

// ---------------- tf32 tensor-core GEMM ------------------------------------
// 128x128x32 tiles, 3-stage cp.async ring, 256 threads (8 warps, 2x4),
// warp tile 64x32. No cvt: raw f32 fed to tf32 mma (HW truncates).
// flipMode: 0 none; 1 flip A rows when z==1; 2 dual-A (K split at 512:
//           k<512 reads A0[m], k>=512 reads A1[m^1023]).
// epi: 0 none; 1 softplus(v+bias[c]); 2 v+bias[c]+resid[r*N+c].

#define AS_STRIDE 36
#define BS_STRIDE 136
#define STAGES 3
#define SMEM_BYTES (STAGES * (128*AS_STRIDE + 32*BS_STRIDE) * 4)

__device__ __forceinline__ unsigned cvta_s(const void* p) {
    return (unsigned)__cvta_generic_to_shared(p);
}
__device__ __forceinline__ void cp16(unsigned dst, const void* src, int srcbytes) {
    asm volatile("cp.async.cg.shared.global [%0], [%1], 16, %2;\n"
                 :: "r"(dst), "l"(src), "r"(srcbytes));
}

__global__ __launch_bounds__(256)
void mma_gemm(const float* __restrict__ A0, const float* __restrict__ A1, int lda, int flipMode,
              const float* __restrict__ W0, const float* __restrict__ W1, int ldw,
              float* __restrict__ C0, float* __restrict__ C1, int ldc, int flipC, int coffz,
              int N, int K, int epi,
              const float* __restrict__ bias0, const float* __restrict__ bias1,
              const float* __restrict__ resid)
{
    extern __shared__ float smem[];
    float* As = smem;                                  // [STAGES][128][AS_STRIDE]
    float* Bs = smem + STAGES * 128 * AS_STRIDE;       // [STAGES][32][BS_STRIDE]

    const int z = blockIdx.z;
    const float* A = z ? A1 : A0;
    const float* W = z ? W1 : W0;
    float*       C = z ? C1 : C0;
    const float* bias = z ? bias1 : bias0;
    const bool dual = (flipMode == 2);
    const int fA = (flipMode == 1 && z);
    const int fC = (flipC && z);
    const int coff = coffz * z;

    const int tid = threadIdx.x;
    const int m0 = blockIdx.x * 128;
    const int n0 = blockIdx.y * 128;

    const int ar  = tid >> 1;
    const int akc = (tid & 1) * 16;
    int gm = m0 + ar;
    if (fA) gm ^= (LSEQ - 1);
    const float* A0row = A + (size_t)gm * lda;
    const float* A1row = dual ? (A1 + (size_t)(gm ^ (LSEQ - 1)) * lda) : nullptr;

    const int bkr = tid >> 3;
    const int bnc = (tid & 7) * 16;

    const int wid = tid >> 5, lane = tid & 31;
    const int wm = wid & 1, wn = wid >> 1;
    const int lr = lane >> 2, lc = lane & 3;

    float acc[4][4][4];
    #pragma unroll
    for (int mi = 0; mi < 4; mi++)
        #pragma unroll
        for (int ni = 0; ni < 4; ni++)
            #pragma unroll
            for (int q = 0; q < 4; q++) acc[mi][ni][q] = 0.f;

    const int nk = (K + 31) >> 5;

    auto loadA = [&](int kk, int buf) {
        float* dst = As + buf * (128 * AS_STRIDE) + ar * AS_STRIDE + akc;
        #pragma unroll
        for (int j = 0; j < 4; j++) {
            int kg = kk + akc + j * 4;
            int sb = (kg < K) ? 16 : 0;
            const float* src;
            if (dual && kg >= 512) src = A1row + (kg - 512);
            else                   src = A0row + (sb ? kg : 0);
            cp16(cvta_s(dst + j * 4), src, sb);
        }
    };
    auto loadB = [&](int kk, int buf) {
        int kg = kk + bkr;
        int inK = (kg < K);
        const float* srow = W + (size_t)(inK ? kg : 0) * ldw;
        float* dst = Bs + buf * (32 * BS_STRIDE) + bkr * BS_STRIDE + bnc;
        #pragma unroll
        for (int j = 0; j < 4; j++) {
            int gn = n0 + bnc + j * 4;
            int sb = (inK && gn < N) ? 16 : 0;
            cp16(cvta_s(dst + j * 4), srow + (sb ? gn : 0), sb);
        }
    };

    // prologue: stage 0 and 1
    loadA(0, 0); loadB(0, 0);
    asm volatile("cp.async.commit_group;\n");
    loadA(32, 1); loadB(32, 1);
    asm volatile("cp.async.commit_group;\n");

    int buf = 0;
    for (int t = 0; t < nk; t++) {
        asm volatile("cp.async.wait_group %0;\n" :: "n"(STAGES - 2));
        __syncthreads();

        // prefetch stage t+2 into the buffer freed at iteration t-1
        if (t + STAGES - 1 < nk) {
            int nb = buf + (STAGES - 1); if (nb >= STAGES) nb -= STAGES;
            loadA((t + STAGES - 1) << 5, nb);
            loadB((t + STAGES - 1) << 5, nb);
        }
        asm volatile("cp.async.commit_group;\n");

        const float* AsB = As + buf * (128 * AS_STRIDE);
        const float* BsB = Bs + buf * (32 * BS_STRIDE);

        #pragma unroll
        for (int s = 0; s < 4; s++) {
            unsigned af[4][4], bf[4][2];
            #pragma unroll
            for (int mi = 0; mi < 4; mi++) {
                const float* p = AsB + (wm * 64 + mi * 16 + lr) * AS_STRIDE + s * 8 + lc;
                af[mi][0] = __float_as_uint(p[0]);
                af[mi][1] = __float_as_uint(p[8 * AS_STRIDE]);
                af[mi][2] = __float_as_uint(p[4]);
                af[mi][3] = __float_as_uint(p[8 * AS_STRIDE + 4]);
            }
            #pragma unroll
            for (int ni = 0; ni < 4; ni++) {
                const float* p = BsB + (s * 8 + lc) * BS_STRIDE + wn * 32 + ni * 8 + lr;
                bf[ni][0] = __float_as_uint(p[0]);
                bf[ni][1] = __float_as_uint(p[4 * BS_STRIDE]);
            }
            #pragma unroll
            for (int mi = 0; mi < 4; mi++)
                #pragma unroll
                for (int ni = 0; ni < 4; ni++) {
                    asm volatile(
                        "mma.sync.aligned.m16n8k8.row.col.f32.tf32.tf32.f32 "
                        "{%0,%1,%2,%3},{%4,%5,%6,%7},{%8,%9},{%0,%1,%2,%3};\n"
                        : "+f"(acc[mi][ni][0]), "+f"(acc[mi][ni][1]),
                          "+f"(acc[mi][ni][2]), "+f"(acc[mi][ni][3])
                        : "r"(af[mi][0]), "r"(af[mi][1]), "r"(af[mi][2]), "r"(af[mi][3]),
                          "r"(bf[ni][0]), "r"(bf[ni][1]));
                }
        }
        buf++; if (buf >= STAGES) buf = 0;
    }

    #pragma unroll
    for (int mi = 0; mi < 4; mi++) {
        int r0r = m0 + wm * 64 + mi * 16 + lr;
        #pragma unroll
        for (int ni = 0; ni < 4; ni++) {
            int cb = n0 + wn * 32 + ni * 8 + 2 * lc;
            #pragma unroll
            for (int q = 0; q < 4; q++) {
                int r = r0r + (q >> 1) * 8;
                int c = cb + (q & 1);
                if (c < N) {
                    float v = acc[mi][ni][q];
                    if (epi == 1) {
                        v += bias[c];
                        v = (v > 20.f) ? v : log1pf(__expf(v));
                    } else if (epi == 2) {
                        v += bias[c] + resid[(size_t)r * N + c];
                    }
                    int cr = fC ? (r ^ (LSEQ - 1)) : r;
                    C[(size_t)cr * ldc + coff + c] = v;
                }
            }
        }
    }
}

// ---------------- causal depthwise conv (DC=4) + bias + SiLU ---------------
__global__ void conv_silu_kernel(const float* __restrict__ xr0, const float* __restrict__ xr1,
                                 const float* __restrict__ cw0, const float* __restrict__ cw1,
                                 const float* __restrict__ cb0, const float* __restrict__ cb1,
                                 float* __restrict__ xsc0, float* __restrict__ xsc1)
{
    int dir = blockIdx.y;
    const float* xr = dir ? xr1 : xr0;
    const float* cw = dir ? cw1 : cw0;
    const float* cb = dir ? cb1 : cb0;
    float* xsc = dir ? xsc1 : xsc0;

    int idx = blockIdx.x * 256 + threadIdx.x;
    int row = idx >> 9;
    int c   = idx & (DI - 1);
    int tau = row & (LSEQ - 1);
    const float* p = xr + (size_t)row * (2 * DI) + c;
    float w0 = cw[c * 4 + 0], w1 = cw[c * 4 + 1], w2 = cw[c * 4 + 2], w3 = cw[c * 4 + 3];
    float acc = cb[c];
    if (tau >= 3) acc = fmaf(p[-3 * 2 * DI], w0, acc);
    if (tau >= 2) acc = fmaf(p[-2 * 2 * DI], w1, acc);
    if (tau >= 1) acc = fmaf(p[-1 * 2 * DI], w2, acc);
    acc = fmaf(p[0], w3, acc);
    float sv = acc / (1.f + __expf(-acc));
    xsc[(size_t)row * DI + c] = sv;
}

// ---------------- chunked selective scan -----------------------------------
__device__ __forceinline__ void powers16(float q, float* p) {
    p[0] = q;        p[1] = q * q;     p[2] = p[1] * q;   p[3] = p[1] * p[1];
    p[4] = p[3] * q; p[5] = p[3] * p[1]; p[6] = p[3] * p[2]; p[7] = p[3] * p[3];
    p[8]  = p[7] * q;    p[9]  = p[7] * p[1]; p[10] = p[7] * p[2]; p[11] = p[7] * p[3];
    p[12] = p[7] * p[4]; p[13] = p[7] * p[5]; p[14] = p[7] * p[6]; p[15] = p[7] * p[7];
}

__device__ __forceinline__ bool load_a(const float* __restrict__ ALog, int d, float* a) {
    #pragma unroll
    for (int n = 0; n < 16; n++) a[n] = -__expf(ALog[d * 16 + n]);
    bool fast = true;
    float a1 = a[0];
    #pragma unroll
    for (int n = 1; n < 16; n++)
        fast = fast && (fabsf(a[n] - (n + 1) * a1) <= 1e-4f * fabsf((n + 1) * a1));
    return fast;
}

__global__ __launch_bounds__(128)
void scanA_kernel(const float* __restrict__ xdbl0, const float* __restrict__ xdbl1,
                  const float* __restrict__ delta0, const float* __restrict__ delta1,
                  const float* __restrict__ xsc0, const float* __restrict__ xsc1,
                  const float* __restrict__ ALog0, const float* __restrict__ ALog1,
                  float* __restrict__ y0, float* __restrict__ y1,
                  float* __restrict__ hfin, float* __restrict__ dSb)
{
    int zb  = blockIdx.z;
    int dir = zb >> 3;
    const float* xdbl  = dir ? xdbl1  : xdbl0;
    const float* delta = dir ? delta1 : delta0;
    const float* xsc   = dir ? xsc1   : xsc0;
    const float* ALog  = dir ? ALog1  : ALog0;
    float* y           = dir ? y1     : y0;

    int ch  = blockIdx.y;
    int tid = threadIdx.x;
    int d   = blockIdx.x * 128 + tid;
    int b   = zb & 7;
    int base = b * LSEQ + ch * CH;

    __shared__ float sBC[CH][32];
    for (int i = tid; i < CH * 8; i += 128) {
        int tt = i >> 3, q = i & 7;
        *(float4*)&sBC[tt][q * 4] =
            *(const float4*)&xdbl[(size_t)(base + tt) * XDBLC + DTR + q * 4];
    }
    __syncthreads();

    float a[16];
    bool fast = load_a(ALog, d, a);
    float a1 = a[0];

    float h[16];
    #pragma unroll
    for (int n = 0; n < 16; n++) h[n] = 0.f;
    float S = 0.f;

    const float* dp = delta + (size_t)base * DI + d;
    const float* xp = xsc   + (size_t)base * DI + d;
    float* yp       = y     + (size_t)base * DI + d;

    if (fast) {
        #pragma unroll 2
        for (int t = 0; t < CH; t++) {
            float dlt = dp[(size_t)t * DI];
            float xv  = xp[(size_t)t * DI];
            S += dlt;
            float dx = dlt * xv;
            float p[16];
            powers16(__expf(dlt * a1), p);
            float yv = 0.f;
            #pragma unroll
            for (int n = 0; n < 16; n++) {
                h[n] = fmaf(p[n], h[n], dx * sBC[t][n]);
                yv   = fmaf(h[n], sBC[t][16 + n], yv);
            }
            yp[(size_t)t * DI] = yv;
        }
    } else {
        for (int t = 0; t < CH; t++) {
            float dlt = dp[(size_t)t * DI];
            float xv  = xp[(size_t)t * DI];
            S += dlt;
            float dx = dlt * xv;
            float yv = 0.f;
            #pragma unroll
            for (int n = 0; n < 16; n++) {
                float dA = __expf(dlt * a[n]);
                h[n] = fmaf(dA, h[n], dx * sBC[t][n]);
                yv   = fmaf(h[n], sBC[t][16 + n], yv);
            }
            yp[(size_t)t * DI] = yv;
        }
    }

    size_t cc = (size_t)(zb * NCH + ch);
    #pragma unroll
    for (int n = 0; n < 16; n++) hfin[cc * 8192 + n * 512 + d] = h[n];
    dSb[cc * 512 + d] = S;
}

__global__ void scanB_kernel(float* __restrict__ hfin, const float* __restrict__ dSb,
                             const float* __restrict__ ALog0, const float* __restrict__ ALog1)
{
    int idx = blockIdx.x * 256 + threadIdx.x;
    int d  = idx & 511;
    int zb = idx >> 9;
    const float* ALog = (zb >> 3) ? ALog1 : ALog0;

    float a[16];
    bool fast = load_a(ALog, d, a);
    float a1 = a[0];

    float hin[16];
    #pragma unroll
    for (int n = 0; n < 16; n++) hin[n] = 0.f;

    for (int c = 0; c < NCH; c++) {
        size_t cc = (size_t)(zb * NCH + c);
        float S = dSb[cc * 512 + d];
        float P[16];
        if (fast) {
            powers16(__expf(S * a1), P);
        } else {
            #pragma unroll
            for (int n = 0; n < 16; n++) P[n] = __expf(S * a[n]);
        }
        #pragma unroll
        for (int n = 0; n < 16; n++) {
            float hf = hfin[cc * 8192 + n * 512 + d];
            hfin[cc * 8192 + n * 512 + d] = hin[n];
            hin[n] = fmaf(P[n], hin[n], hf);
        }
    }
}

__global__ __launch_bounds__(128)
void scanC_kernel(const float* __restrict__ xdbl0, const float* __restrict__ xdbl1,
                  const float* __restrict__ delta0, const float* __restrict__ delta1,
                  const float* __restrict__ xsc0, const float* __restrict__ xsc1,
                  const float* __restrict__ xr0, const float* __restrict__ xr1,
                  const float* __restrict__ ALog0, const float* __restrict__ ALog1,
                  const float* __restrict__ Dp0, const float* __restrict__ Dp1,
                  float* __restrict__ y0, float* __restrict__ y1,
                  const float* __restrict__ hfin)
{
    int zb  = blockIdx.z;
    int dir = zb >> 3;
    const float* xdbl  = dir ? xdbl1  : xdbl0;
    const float* delta = dir ? delta1 : delta0;
    const float* xsc   = dir ? xsc1   : xsc0;
    const float* xr    = dir ? xr1    : xr0;
    const float* ALog  = dir ? ALog1  : ALog0;
    const float* Dp    = dir ? Dp1    : Dp0;
    float* y           = dir ? y1     : y0;

    int ch  = blockIdx.y;
    int tid = threadIdx.x;
    int d   = blockIdx.x * 128 + tid;
    int b   = zb & 7;
    int base = b * LSEQ + ch * CH;

    __shared__ float sC[CH][16];
    for (int i = tid; i < CH * 4; i += 128) {
        int tt = i >> 2, q = i & 3;
        *(float4*)&sC[tt][q * 4] =
            *(const float4*)&xdbl[(size_t)(base + tt) * XDBLC + DTR + DS + q * 4];
    }
    __syncthreads();

    float a[16];
    bool fast = load_a(ALog, d, a);
    float a1 = a[0];
    float Dv = Dp[d];

    size_t cc = (size_t)(zb * NCH + ch);
    float w[16];
    bool zero = true;
    #pragma unroll
    for (int n = 0; n < 16; n++) {
        w[n] = hfin[cc * 8192 + n * 512 + d];
        zero = zero && (w[n] == 0.f);
    }

    const float* dp = delta + (size_t)base * DI + d;
    const float* xp = xsc   + (size_t)base * DI + d;
    const float* rp = xr    + (size_t)base * (2 * DI) + DI + d;
    float* yp       = y     + (size_t)base * DI + d;

    if (zero) {
        #pragma unroll 4
        for (int t = 0; t < CH; t++) {
            float xv  = xp[(size_t)t * DI];
            float res = rp[(size_t)t * (2 * DI)];
            float yl  = yp[(size_t)t * DI];
            float sres = res / (1.f + __expf(-res));
            yp[(size_t)t * DI] = (yl + Dv * xv) * sres;
        }
    } else if (fast) {
        float r = 1.f;
        #pragma unroll 2
        for (int t = 0; t < CH; t++) {
            float dlt = dp[(size_t)t * DI];
            float xv  = xp[(size_t)t * DI];
            float res = rp[(size_t)t * (2 * DI)];
            float yl  = yp[(size_t)t * DI];
            r *= __expf(dlt * a1);
            float p[16];
            powers16(r, p);
            float corr = 0.f;
            #pragma unroll
            for (int n = 0; n < 16; n++)
                corr = fmaf(w[n] * p[n], sC[t][n], corr);
            float sres = res / (1.f + __expf(-res));
            yp[(size_t)t * DI] = (yl + corr + Dv * xv) * sres;
        }
    } else {
        float S = 0.f;
        for (int t = 0; t < CH; t++) {
            float dlt = dp[(size_t)t * DI];
            float xv  = xp[(size_t)t * DI];
            float res = rp[(size_t)t * (2 * DI)];
            float yl  = yp[(size_t)t * DI];
            S += dlt;
            float corr = 0.f;
            #pragma unroll
            for (int n = 0; n < 16; n++)
                corr = fmaf(w[n] * __expf(S * a[n]), sC[t][n], corr);
            float sres = res / (1.f + __expf(-res));
            yp[(size_t)t * DI] = (yl + corr + Dv * xv) * sres;
        }
    }
}

// ---------------- launcher -------------------------------------------------
extern "C" void kernel_launch(void* const* d_in, const int* in_sizes, int n_in,
                              void* d_out, int out_size)
{
    const float* x      = (const float*)d_in[0];
    const float* norm_g = (const float*)d_in[1];
    const float* norm_b = (const float*)d_in[2];
    const float* inW[2]   = {(const float*)d_in[3],  (const float*)d_in[12]};
    const float* convW[2] = {(const float*)d_in[4],  (const float*)d_in[13]};
    const float* convB[2] = {(const float*)d_in[5],  (const float*)d_in[14]};
    const float* xW[2]    = {(const float*)d_in[6],  (const float*)d_in[15]};
    const float* dtW[2]   = {(const float*)d_in[7],  (const float*)d_in[16]};
    const float* dtB[2]   = {(const float*)d_in[8],  (const float*)d_in[17]};
    const float* ALog[2]  = {(const float*)d_in[9],  (const float*)d_in[18]};
    const float* Dp[2]    = {(const float*)d_in[10], (const float*)d_in[19]};
    const float* outW[2]  = {(const float*)d_in[11], (const float*)d_in[20]};
    const float* fusW = (const float*)d_in[21];
    const float* fusB = (const float*)d_in[22];
    float* out = (float*)d_out;

    float* base = nullptr;
    cudaGetSymbolAddress((void**)&base, g_buf);
    float* xn        = base + OFF_XN;
    float* xr_[2]    = {base + OFF_XR,    base + OFF_XR    + (size_t)BL * 2 * DI};
    float* xsc_[2]   = {base + OFF_XSC,   base + OFF_XSC   + (size_t)BL * DI};
    float* xdbl_[2]  = {base + OFF_XDBL,  base + OFF_XDBL  + (size_t)BL * XDBLC};
    float* delta_[2] = {base + OFF_DELTA, base + OFF_DELTA + (size_t)BL * DI};
    float* y_[2]     = {base + OFF_Y,     base + OFF_Y     + (size_t)BL * DI};
    float* Wcomb     = base + OFF_WC;
    float* hfin      = base + OFF_HF;
    float* dSb       = base + OFF_DS;

    static bool attr_set = false;
    if (!attr_set) {
        cudaFuncSetAttribute(mma_gemm, cudaFuncAttributeMaxDynamicSharedMemorySize, SMEM_BYTES);
        attr_set = true;
    }

    // 0) combined out+fuse weights: Cf = outW_f @ fusW_top, Cb = outW_b @ fusW_bot
    mma_gemm<<<dim3(4, 2, 2), 256, SMEM_BYTES>>>(
        outW[0], outW[1], DM, 0,
        fusW, fusW + (size_t)DM * DM, DM,
        Wcomb, Wcomb + (size_t)512 * DM, DM, 0, 0,
        DM, DM, 0, nullptr, nullptr, nullptr);

    // 1) LayerNorm
    ln_kernel<<<BL, 256>>>(x, norm_g, norm_b, xn);

    // 2) in_proj, both dirs (flip A rows for backward)
    mma_gemm<<<dim3(BL / 128, 8, 2), 256, SMEM_BYTES>>>(
        xn, xn, DM, 1,
        inW[0], inW[1], 2 * DI,
        xr_[0], xr_[1], 2 * DI, 0, 0,
        2 * DI, DM, 0, nullptr, nullptr, nullptr);

    // 3) causal dw-conv + silu, both dirs
    conv_silu_kernel<<<dim3((BL * DI) / 256, 2), 256>>>(
        xr_[0], xr_[1], convW[0], convW[1], convB[0], convB[1], xsc_[0], xsc_[1]);

    // 4) x_proj -> [dlt | B | C], both dirs
    mma_gemm<<<dim3(BL / 128, 1, 2), 256, SMEM_BYTES>>>(
        xsc_[0], xsc_[1], DI, 0,
        xW[0], xW[1], XDBLC,
        xdbl_[0], xdbl_[1], XDBLC, 0, 0,
        XDBLC, DI, 0, nullptr, nullptr, nullptr);

    // 5) delta = softplus(dlt @ dtW + dtB), both dirs
    mma_gemm<<<dim3(BL / 128, 4, 2), 256, SMEM_BYTES>>>(
        xdbl_[0], xdbl_[1], XDBLC, 0,
        dtW[0], dtW[1], DI,
        delta_[0], delta_[1], DI, 0, 0,
        DI, DTR, 1, dtB[0], dtB[1], nullptr);

    // 6) chunked scan: local -> combine -> correct+gate
    scanA_kernel<<<dim3(DI / 128, NCH, 16), 128>>>(
        xdbl_[0], xdbl_[1], delta_[0], delta_[1], xsc_[0], xsc_[1],
        ALog[0], ALog[1], y_[0], y_[1], hfin, dSb);
    scanB_kernel<<<32, 256>>>(hfin, dSb, ALog[0], ALog[1]);
    scanC_kernel<<<dim3(DI / 128, NCH, 16), 128>>>(
        xdbl_[0], xdbl_[1], delta_[0], delta_[1], xsc_[0], xsc_[1],
        xr_[0], xr_[1], ALog[0], ALog[1], Dp[0], Dp[1], y_[0], y_[1], hfin);

    // 7) combined out_proj + fuse + residual (dual-A, K=1024):
    //    out[m] = x[m] + fusB + y_f[m] @ Cf + y_b[m^1023] @ Cb
    mma_gemm<<<dim3(BL / 128, 2, 1), 256, SMEM_BYTES>>>(
        y_[0], y_[1], DI, 2,
        Wcomb, Wcomb, DM,
        out, out, DM, 0, 0,
        DM, 1024, 2, fusB, fusB, x);
}

// round 6
// speedup vs baseline: 1.1863x; 1.1863x over previous
#include <cuda_runtime.h>
#include <cstdint>

#define BATCH 8
#define LSEQ  1024
#define DM    256
#define DS    16
#define DC    4
#define DI    512
#define DTR   16
#define BL    (BATCH * LSEQ)   // 8192
#define XDBLC (DTR + 2 * DS)   // 48
#define CH    128
#define NCH   (LSEQ / CH)      // 8

// ---------------- scratch (single static device buffer; no allocations) ---
static const size_t OFF_XN    = 0;
static const size_t OFF_XR    = OFF_XN    + (size_t)BL * DM;
static const size_t OFF_XSC   = OFF_XR    + (size_t)2 * BL * 2 * DI;
static const size_t OFF_XDBL  = OFF_XSC   + (size_t)2 * BL * DI;
static const size_t OFF_Y     = OFF_XDBL  + (size_t)2 * BL * XDBLC;
static const size_t OFF_WC    = OFF_Y     + (size_t)2 * BL * DI;     // combined weights 1024x256
static const size_t OFF_HF    = OFF_WC    + (size_t)1024 * 256;
static const size_t OFF_DS    = OFF_HF    + (size_t)2 * 8 * NCH * 16 * 512;
static const size_t TOTAL_F   = OFF_DS    + (size_t)2 * 8 * NCH * 512;

__device__ float g_buf[TOTAL_F];

// ---------------- LayerNorm: warp per token, float4 ------------------------
__global__ __launch_bounds__(256)
void ln_kernel(const float* __restrict__ x,
               const float* __restrict__ g,
               const float* __restrict__ b,
               float* __restrict__ xn)
{
    int warp = threadIdx.x >> 5, lane = threadIdx.x & 31;
    int tok = blockIdx.x * 8 + warp;
    const float4* xp = (const float4*)(x + (size_t)tok * DM) + lane * 2;
    float4 u0 = xp[0], u1 = xp[1];
    float s  = u0.x + u0.y + u0.z + u0.w + u1.x + u1.y + u1.z + u1.w;
    float s2 = u0.x*u0.x + u0.y*u0.y + u0.z*u0.z + u0.w*u0.w
             + u1.x*u1.x + u1.y*u1.y + u1.z*u1.z + u1.w*u1.w;
    #pragma unroll
    for (int o = 16; o; o >>= 1) {
        s  += __shfl_xor_sync(0xffffffffu, s,  o);
        s2 += __shfl_xor_sync(0xffffffffu, s2, o);
    }
    float mu  = s * (1.0f / DM);
    float var = s2 * (1.0f / DM) - mu * mu;
    float r = rsqrtf(var + 1e-5f);
    const float4* gp = (const float4*)g + lane * 2;
    const float4* bp = (const float4*)b + lane * 2;
    float4 g0 = gp[0], g1 = gp[1], b0 = bp[0], b1 = bp[1];
    float4 o0, o1;
    o0.x = (u0.x - mu) * r * g0.x + b0.x;  o0.y = (u0.y - mu) * r * g0.y + b0.y;
    o0.z = (u0.z - mu) * r * g0.z + b0.z;  o0.w = (u0.w - mu) * r * g0.w + b0.w;
    o1.x = (u1.x - mu) * r * g1.x + b1.x;  o1.y = (u1.y - mu) * r * g1.y + b1.y;
    o1.z = (u1.z - mu) * r * g1.z + b1.z;  o1.w = (u1.w - mu) * r * g1.w + b1.w;
    float4* op = (float4*)(xn + (size_t)tok * DM) + lane * 2;
    op[0] = o0; op[1] = o1;
}

// ---------------- tf32 tensor-core GEMM ------------------------------------
// 128x128x32 tiles, 3-stage cp.async ring, 256 threads (8 warps, 2x4),
// warp tile 64x32. A fragments via ldmatrix.x4.b16 (bitwise f32/tf32).
// flipMode: 0 none; 1 flip A rows when z==1; 2 dual-A (K split at 512).
// epi: 0 none; 2 v + bias[c] + resid[r*N+c].

#define AS_STRIDE 36
#define BS_STRIDE 136
#define STAGES 3
#define SMEM_BYTES (STAGES * (128*AS_STRIDE + 32*BS_STRIDE) * 4)

__device__ __forceinline__ unsigned cvta_s(const void* p) {
    return (unsigned)__cvta_generic_to_shared(p);
}
__device__ __forceinline__ void cp16(unsigned dst, const void* src, int srcbytes) {
    asm volatile("cp.async.cg.shared.global [%0], [%1], 16, %2;\n"
                 :: "r"(dst), "l"(src), "r"(srcbytes));
}

__global__ __launch_bounds__(256)
void mma_gemm(const float* __restrict__ A0, const float* __restrict__ A1, int lda, int flipMode,
              const float* __restrict__ W0, const float* __restrict__ W1, int ldw,
              float* __restrict__ C0, float* __restrict__ C1, int ldc, int flipC, int coffz,
              int N, int K, int epi,
              const float* __restrict__ bias0, const float* __restrict__ bias1,
              const float* __restrict__ resid)
{
    extern __shared__ float smem[];
    float* As = smem;                                  // [STAGES][128][AS_STRIDE]
    float* Bs = smem + STAGES * 128 * AS_STRIDE;       // [STAGES][32][BS_STRIDE]

    const int z = blockIdx.z;
    const float* A = z ? A1 : A0;
    const float* W = z ? W1 : W0;
    float*       C = z ? C1 : C0;
    const float* bias = z ? bias1 : bias0;
    const bool dual = (flipMode == 2);
    const int fA = (flipMode == 1 && z);
    const int fC = (flipC && z);
    const int coff = coffz * z;

    const int tid = threadIdx.x;
    const int m0 = blockIdx.x * 128;
    const int n0 = blockIdx.y * 128;

    const int ar  = tid >> 1;
    const int akc = (tid & 1) * 16;
    int gm = m0 + ar;
    if (fA) gm ^= (LSEQ - 1);
    const float* A0row = A + (size_t)gm * lda;
    const float* A1row = dual ? (A1 + (size_t)(gm ^ (LSEQ - 1)) * lda) : nullptr;

    const int bkr = tid >> 3;
    const int bnc = (tid & 7) * 16;

    const int wid = tid >> 5, lane = tid & 31;
    const int wm = wid & 1, wn = wid >> 1;
    const int lr = lane >> 2, lc = lane & 3;
    // ldmatrix lane addressing: quadrants (rows, rows+8, cols+4, both)
    const int grp = lane >> 3, lrow = lane & 7;
    const int lm_row = wm * 64 + (grp & 1) * 8 + lrow;
    const int lm_col = (grp >> 1) * 4;

    float acc[4][4][4];
    #pragma unroll
    for (int mi = 0; mi < 4; mi++)
        #pragma unroll
        for (int ni = 0; ni < 4; ni++)
            #pragma unroll
            for (int q = 0; q < 4; q++) acc[mi][ni][q] = 0.f;

    const int nk = (K + 31) >> 5;

    auto loadA = [&](int kk, int buf) {
        float* dst = As + buf * (128 * AS_STRIDE) + ar * AS_STRIDE + akc;
        #pragma unroll
        for (int j = 0; j < 4; j++) {
            int kg = kk + akc + j * 4;
            int sb = (kg < K) ? 16 : 0;
            const float* src;
            if (dual && kg >= 512) src = A1row + (kg - 512);
            else                   src = A0row + (sb ? kg : 0);
            cp16(cvta_s(dst + j * 4), src, sb);
        }
    };
    auto loadB = [&](int kk, int buf) {
        int kg = kk + bkr;
        int inK = (kg < K);
        const float* srow = W + (size_t)(inK ? kg : 0) * ldw;
        float* dst = Bs + buf * (32 * BS_STRIDE) + bkr * BS_STRIDE + bnc;
        #pragma unroll
        for (int j = 0; j < 4; j++) {
            int gn = n0 + bnc + j * 4;
            int sb = (inK && gn < N) ? 16 : 0;
            cp16(cvta_s(dst + j * 4), srow + (sb ? gn : 0), sb);
        }
    };

    loadA(0, 0); loadB(0, 0);
    asm volatile("cp.async.commit_group;\n");
    loadA(32, 1); loadB(32, 1);
    asm volatile("cp.async.commit_group;\n");

    int buf = 0;
    for (int t = 0; t < nk; t++) {
        asm volatile("cp.async.wait_group %0;\n" :: "n"(STAGES - 2));
        __syncthreads();

        if (t + STAGES - 1 < nk) {
            int nb = buf + (STAGES - 1); if (nb >= STAGES) nb -= STAGES;
            loadA((t + STAGES - 1) << 5, nb);
            loadB((t + STAGES - 1) << 5, nb);
        }
        asm volatile("cp.async.commit_group;\n");

        const float* AsB = As + buf * (128 * AS_STRIDE);
        const float* BsB = Bs + buf * (32 * BS_STRIDE);
        unsigned as_lane = cvta_s(AsB) + (unsigned)((lm_row * AS_STRIDE + lm_col) * 4);

        #pragma unroll
        for (int s = 0; s < 4; s++) {
            unsigned af[4][4], bf[4][2];
            #pragma unroll
            for (int mi = 0; mi < 4; mi++) {
                unsigned a_addr = as_lane + (unsigned)(((mi * 16) * AS_STRIDE + s * 8) * 4);
                asm volatile(
                    "ldmatrix.sync.aligned.m8n8.x4.shared.b16 {%0,%1,%2,%3}, [%4];\n"
                    : "=r"(af[mi][0]), "=r"(af[mi][1]), "=r"(af[mi][2]), "=r"(af[mi][3])
                    : "r"(a_addr));
            }
            const float* bp = BsB + (s * 8 + lc) * BS_STRIDE + wn * 32 + lr;
            #pragma unroll
            for (int ni = 0; ni < 4; ni++) {
                bf[ni][0] = __float_as_uint(bp[ni * 8]);
                bf[ni][1] = __float_as_uint(bp[ni * 8 + 4 * BS_STRIDE]);
            }
            #pragma unroll
            for (int mi = 0; mi < 4; mi++)
                #pragma unroll
                for (int ni = 0; ni < 4; ni++) {
                    asm volatile(
                        "mma.sync.aligned.m16n8k8.row.col.f32.tf32.tf32.f32 "
                        "{%0,%1,%2,%3},{%4,%5,%6,%7},{%8,%9},{%0,%1,%2,%3};\n"
                        : "+f"(acc[mi][ni][0]), "+f"(acc[mi][ni][1]),
                          "+f"(acc[mi][ni][2]), "+f"(acc[mi][ni][3])
                        : "r"(af[mi][0]), "r"(af[mi][1]), "r"(af[mi][2]), "r"(af[mi][3]),
                          "r"(bf[ni][0]), "r"(bf[ni][1]));
                }
        }
        buf++; if (buf >= STAGES) buf = 0;
    }

    #pragma unroll
    for (int mi = 0; mi < 4; mi++) {
        int r0r = m0 + wm * 64 + mi * 16 + lr;
        #pragma unroll
        for (int ni = 0; ni < 4; ni++) {
            int cb = n0 + wn * 32 + ni * 8 + 2 * lc;
            #pragma unroll
            for (int q = 0; q < 4; q++) {
                int r = r0r + (q >> 1) * 8;
                int c = cb + (q & 1);
                if (c < N) {
                    float v = acc[mi][ni][q];
                    if (epi == 2)
                        v += bias[c] + resid[(size_t)r * N + c];
                    int cr = fC ? (r ^ (LSEQ - 1)) : r;
                    C[(size_t)cr * ldc + coff + c] = v;
                }
            }
        }
    }
}

// ---------------- causal depthwise conv (DC=4) + bias + SiLU ---------------
// 4 outputs per thread (sliding window: 7 loads -> 4 outputs)
__global__ __launch_bounds__(256)
void conv_silu_kernel(const float* __restrict__ xr0, const float* __restrict__ xr1,
                      const float* __restrict__ cw0, const float* __restrict__ cw1,
                      const float* __restrict__ cb0, const float* __restrict__ cb1,
                      float* __restrict__ xsc0, float* __restrict__ xsc1)
{
    int dir = blockIdx.y;
    const float* xr = dir ? xr1 : xr0;
    const float* cw = dir ? cw1 : cw0;
    const float* cb = dir ? cb1 : cb0;
    float* xsc = dir ? xsc1 : xsc0;

    int idx = blockIdx.x * 256 + threadIdx.x;     // BL/4 * DI threads
    int c   = idx & (DI - 1);
    int rb  = idx >> 9;                            // 0 .. BL/4-1
    int t0  = rb * 4;
    int tau0 = t0 & (LSEQ - 1);

    const float* p = xr + (size_t)t0 * (2 * DI) + c;
    float w0 = cw[c * 4 + 0], w1 = cw[c * 4 + 1], w2 = cw[c * 4 + 2], w3 = cw[c * 4 + 3];
    float bias = cb[c];

    float v[7];
    #pragma unroll
    for (int j = 0; j < 7; j++) {
        int off = j - 3;
        bool valid = (tau0 + off >= 0);
        v[j] = valid ? p[(long)off * 2 * DI] : 0.f;
    }
    float* op = xsc + (size_t)t0 * DI + c;
    #pragma unroll
    for (int k = 0; k < 4; k++) {
        float acc = bias;
        acc = fmaf(v[k],     w0, acc);
        acc = fmaf(v[k + 1], w1, acc);
        acc = fmaf(v[k + 2], w2, acc);
        acc = fmaf(v[k + 3], w3, acc);
        op[(size_t)k * DI] = acc / (1.f + __expf(-acc));
    }
}

// ---------------- chunked selective scan (delta fused in) -------------------
__device__ __forceinline__ void powers16(float q, float* p) {
    p[0] = q;        p[1] = q * q;     p[2] = p[1] * q;   p[3] = p[1] * p[1];
    p[4] = p[3] * q; p[5] = p[3] * p[1]; p[6] = p[3] * p[2]; p[7] = p[3] * p[3];
    p[8]  = p[7] * q;    p[9]  = p[7] * p[1]; p[10] = p[7] * p[2]; p[11] = p[7] * p[3];
    p[12] = p[7] * p[4]; p[13] = p[7] * p[5]; p[14] = p[7] * p[6]; p[15] = p[7] * p[7];
}

__device__ __forceinline__ bool load_a(const float* __restrict__ ALog, int d, float* a) {
    #pragma unroll
    for (int n = 0; n < 16; n++) a[n] = -__expf(ALog[d * 16 + n]);
    bool fast = true;
    float a1 = a[0];
    #pragma unroll
    for (int n = 1; n < 16; n++)
        fast = fast && (fabsf(a[n] - (n + 1) * a1) <= 1e-4f * fabsf((n + 1) * a1));
    return fast;
}

__device__ __forceinline__ float softplus_f(float v) {
    return (v > 20.f) ? v : log1pf(__expf(v));
}

// Phase A: local scan; delta computed in-kernel from xdbl + dtW col.
__global__ __launch_bounds__(128)
void scanA_kernel(const float* __restrict__ xdbl0, const float* __restrict__ xdbl1,
                  const float* __restrict__ xsc0, const float* __restrict__ xsc1,
                  const float* __restrict__ dtW0, const float* __restrict__ dtW1,
                  const float* __restrict__ dtB0, const float* __restrict__ dtB1,
                  const float* __restrict__ ALog0, const float* __restrict__ ALog1,
                  float* __restrict__ y0, float* __restrict__ y1,
                  float* __restrict__ hfin, float* __restrict__ dSb)
{
    int zb  = blockIdx.z;
    int dir = zb >> 3;
    const float* xdbl = dir ? xdbl1 : xdbl0;
    const float* xsc  = dir ? xsc1  : xsc0;
    const float* dtW  = dir ? dtW1  : dtW0;
    const float* dtB  = dir ? dtB1  : dtB0;
    const float* ALog = dir ? ALog1 : ALog0;
    float* y          = dir ? y1    : y0;

    int ch  = blockIdx.y;
    int tid = threadIdx.x;
    int d   = blockIdx.x * 128 + tid;
    int b   = zb & 7;
    int base = b * LSEQ + ch * CH;

    __shared__ float sX[CH][XDBLC];   // all 48 cols: [dlt16 | B16 | C16]
    for (int i = tid; i < CH * 12; i += 128) {
        int tt = i / 12, q = i % 12;
        *(float4*)&sX[tt][q * 4] =
            *(const float4*)&xdbl[(size_t)(base + tt) * XDBLC + q * 4];
    }
    __syncthreads();

    float wreg[16];
    #pragma unroll
    for (int j = 0; j < 16; j++) wreg[j] = dtW[j * DI + d];
    float dbias = dtB[d];

    float a[16];
    bool fast = load_a(ALog, d, a);
    float a1 = a[0];

    float h[16];
    #pragma unroll
    for (int n = 0; n < 16; n++) h[n] = 0.f;
    float S = 0.f;

    const float* xp = xsc + (size_t)base * DI + d;
    float* yp       = y   + (size_t)base * DI + d;

    if (fast) {
        #pragma unroll 2
        for (int t = 0; t < CH; t++) {
            float raw = dbias;
            #pragma unroll
            for (int j = 0; j < 16; j++) raw = fmaf(wreg[j], sX[t][j], raw);
            float dlt = softplus_f(raw);
            float xv  = xp[(size_t)t * DI];
            S += dlt;
            float dx = dlt * xv;
            float p[16];
            powers16(__expf(dlt * a1), p);
            float yv = 0.f;
            #pragma unroll
            for (int n = 0; n < 16; n++) {
                h[n] = fmaf(p[n], h[n], dx * sX[t][16 + n]);
                yv   = fmaf(h[n], sX[t][32 + n], yv);
            }
            yp[(size_t)t * DI] = yv;
        }
    } else {
        for (int t = 0; t < CH; t++) {
            float raw = dbias;
            #pragma unroll
            for (int j = 0; j < 16; j++) raw = fmaf(wreg[j], sX[t][j], raw);
            float dlt = softplus_f(raw);
            float xv  = xp[(size_t)t * DI];
            S += dlt;
            float dx = dlt * xv;
            float yv = 0.f;
            #pragma unroll
            for (int n = 0; n < 16; n++) {
                float dA = __expf(dlt * a[n]);
                h[n] = fmaf(dA, h[n], dx * sX[t][16 + n]);
                yv   = fmaf(h[n], sX[t][32 + n], yv);
            }
            yp[(size_t)t * DI] = yv;
        }
    }

    size_t cc = (size_t)(zb * NCH + ch);
    #pragma unroll
    for (int n = 0; n < 16; n++) hfin[cc * 8192 + n * 512 + d] = h[n];
    dSb[cc * 512 + d] = S;
}

__global__ void scanB_kernel(float* __restrict__ hfin, const float* __restrict__ dSb,
                             const float* __restrict__ ALog0, const float* __restrict__ ALog1)
{
    int idx = blockIdx.x * 256 + threadIdx.x;
    int d  = idx & 511;
    int zb = idx >> 9;
    const float* ALog = (zb >> 3) ? ALog1 : ALog0;

    float a[16];
    bool fast = load_a(ALog, d, a);
    float a1 = a[0];

    float hin[16];
    #pragma unroll
    for (int n = 0; n < 16; n++) hin[n] = 0.f;

    for (int c = 0; c < NCH; c++) {
        size_t cc = (size_t)(zb * NCH + c);
        float S = dSb[cc * 512 + d];
        float P[16];
        if (fast) {
            powers16(__expf(S * a1), P);
        } else {
            #pragma unroll
            for (int n = 0; n < 16; n++) P[n] = __expf(S * a[n]);
        }
        #pragma unroll
        for (int n = 0; n < 16; n++) {
            float hf = hfin[cc * 8192 + n * 512 + d];
            hfin[cc * 8192 + n * 512 + d] = hin[n];
            hin[n] = fmaf(P[n], hin[n], hf);
        }
    }
}

// Phase C: cross-chunk correction + D*x + silu(res) gating; delta recomputed.
__global__ __launch_bounds__(128)
void scanC_kernel(const float* __restrict__ xdbl0, const float* __restrict__ xdbl1,
                  const float* __restrict__ xsc0, const float* __restrict__ xsc1,
                  const float* __restrict__ xr0, const float* __restrict__ xr1,
                  const float* __restrict__ dtW0, const float* __restrict__ dtW1,
                  const float* __restrict__ dtB0, const float* __restrict__ dtB1,
                  const float* __restrict__ ALog0, const float* __restrict__ ALog1,
                  const float* __restrict__ Dp0, const float* __restrict__ Dp1,
                  float* __restrict__ y0, float* __restrict__ y1,
                  const float* __restrict__ hfin)
{
    int zb  = blockIdx.z;
    int dir = zb >> 3;
    const float* xdbl = dir ? xdbl1 : xdbl0;
    const float* xsc  = dir ? xsc1  : xsc0;
    const float* xr   = dir ? xr1   : xr0;
    const float* dtW  = dir ? dtW1  : dtW0;
    const float* dtB  = dir ? dtB1  : dtB0;
    const float* ALog = dir ? ALog1 : ALog0;
    const float* Dp   = dir ? Dp1   : Dp0;
    float* y          = dir ? y1    : y0;

    int ch  = blockIdx.y;
    int tid = threadIdx.x;
    int d   = blockIdx.x * 128 + tid;
    int b   = zb & 7;
    int base = b * LSEQ + ch * CH;

    __shared__ float sX[CH][XDBLC];
    for (int i = tid; i < CH * 12; i += 128) {
        int tt = i / 12, q = i % 12;
        *(float4*)&sX[tt][q * 4] =
            *(const float4*)&xdbl[(size_t)(base + tt) * XDBLC + q * 4];
    }
    __syncthreads();

    float a[16];
    bool fast = load_a(ALog, d, a);
    float a1 = a[0];
    float Dv = Dp[d];

    size_t cc = (size_t)(zb * NCH + ch);
    float w[16];
    bool zero = true;
    #pragma unroll
    for (int n = 0; n < 16; n++) {
        w[n] = hfin[cc * 8192 + n * 512 + d];
        zero = zero && (w[n] == 0.f);
    }

    const float* xp = xsc + (size_t)base * DI + d;
    const float* rp = xr  + (size_t)base * (2 * DI) + DI + d;
    float* yp       = y   + (size_t)base * DI + d;

    if (zero) {
        #pragma unroll 4
        for (int t = 0; t < CH; t++) {
            float xv  = xp[(size_t)t * DI];
            float res = rp[(size_t)t * (2 * DI)];
            float yl  = yp[(size_t)t * DI];
            float sres = res / (1.f + __expf(-res));
            yp[(size_t)t * DI] = (yl + Dv * xv) * sres;
        }
        return;
    }

    float wreg[16];
    #pragma unroll
    for (int j = 0; j < 16; j++) wreg[j] = dtW[j * DI + d];
    float dbias = dtB[d];

    if (fast) {
        float r = 1.f;
        #pragma unroll 2
        for (int t = 0; t < CH; t++) {
            float raw = dbias;
            #pragma unroll
            for (int j = 0; j < 16; j++) raw = fmaf(wreg[j], sX[t][j], raw);
            float dlt = softplus_f(raw);
            float xv  = xp[(size_t)t * DI];
            float res = rp[(size_t)t * (2 * DI)];
            float yl  = yp[(size_t)t * DI];
            r *= __expf(dlt * a1);
            float p[16];
            powers16(r, p);
            float corr = 0.f;
            #pragma unroll
            for (int n = 0; n < 16; n++)
                corr = fmaf(w[n] * p[n], sX[t][32 + n], corr);
            float sres = res / (1.f + __expf(-res));
            yp[(size_t)t * DI] = (yl + corr + Dv * xv) * sres;
        }
    } else {
        float S = 0.f;
        for (int t = 0; t < CH; t++) {
            float raw = dbias;
            #pragma unroll
            for (int j = 0; j < 16; j++) raw = fmaf(wreg[j], sX[t][j], raw);
            float dlt = softplus_f(raw);
            float xv  = xp[(size_t)t * DI];
            float res = rp[(size_t)t * (2 * DI)];
            float yl  = yp[(size_t)t * DI];
            S += dlt;
            float corr = 0.f;
            #pragma unroll
            for (int n = 0; n < 16; n++)
                corr = fmaf(w[n] * __expf(S * a[n]), sX[t][32 + n], corr);
            float sres = res / (1.f + __expf(-res));
            yp[(size_t)t * DI] = (yl + corr + Dv * xv) * sres;
        }
    }
}

// ---------------- launcher -------------------------------------------------
extern "C" void kernel_launch(void* const* d_in, const int* in_sizes, int n_in,
                              void* d_out, int out_size)
{
    const float* x      = (const float*)d_in[0];
    const float* norm_g = (const float*)d_in[1];
    const float* norm_b = (const float*)d_in[2];
    const float* inW[2]   = {(const float*)d_in[3],  (const float*)d_in[12]};
    const float* convW[2] = {(const float*)d_in[4],  (const float*)d_in[13]};
    const float* convB[2] = {(const float*)d_in[5],  (const float*)d_in[14]};
    const float* xW[2]    = {(const float*)d_in[6],  (const float*)d_in[15]};
    const float* dtW[2]   = {(const float*)d_in[7],  (const float*)d_in[16]};
    const float* dtB[2]   = {(const float*)d_in[8],  (const float*)d_in[17]};
    const float* ALog[2]  = {(const float*)d_in[9],  (const float*)d_in[18]};
    const float* Dp[2]    = {(const float*)d_in[10], (const float*)d_in[19]};
    const float* outW[2]  = {(const float*)d_in[11], (const float*)d_in[20]};
    const float* fusW = (const float*)d_in[21];
    const float* fusB = (const float*)d_in[22];
    float* out = (float*)d_out;

    float* base = nullptr;
    cudaGetSymbolAddress((void**)&base, g_buf);
    float* xn        = base + OFF_XN;
    float* xr_[2]    = {base + OFF_XR,    base + OFF_XR    + (size_t)BL * 2 * DI};
    float* xsc_[2]   = {base + OFF_XSC,   base + OFF_XSC   + (size_t)BL * DI};
    float* xdbl_[2]  = {base + OFF_XDBL,  base + OFF_XDBL  + (size_t)BL * XDBLC};
    float* y_[2]     = {base + OFF_Y,     base + OFF_Y     + (size_t)BL * DI};
    float* Wcomb     = base + OFF_WC;
    float* hfin      = base + OFF_HF;
    float* dSb       = base + OFF_DS;

    static bool attr_set = false;
    if (!attr_set) {
        cudaFuncSetAttribute(mma_gemm, cudaFuncAttributeMaxDynamicSharedMemorySize, SMEM_BYTES);
        attr_set = true;
    }

    // 0) combined out+fuse weights: Cf = outW_f @ fusW_top, Cb = outW_b @ fusW_bot
    mma_gemm<<<dim3(4, 2, 2), 256, SMEM_BYTES>>>(
        outW[0], outW[1], DM, 0,
        fusW, fusW + (size_t)DM * DM, DM,
        Wcomb, Wcomb + (size_t)512 * DM, DM, 0, 0,
        DM, DM, 0, nullptr, nullptr, nullptr);

    // 1) LayerNorm
    ln_kernel<<<BL / 8, 256>>>(x, norm_g, norm_b, xn);

    // 2) in_proj, both dirs (flip A rows for backward)
    mma_gemm<<<dim3(BL / 128, 8, 2), 256, SMEM_BYTES>>>(
        xn, xn, DM, 1,
        inW[0], inW[1], 2 * DI,
        xr_[0], xr_[1], 2 * DI, 0, 0,
        2 * DI, DM, 0, nullptr, nullptr, nullptr);

    // 3) causal dw-conv + silu, both dirs (4 outputs/thread)
    conv_silu_kernel<<<dim3((BL / 4) * DI / 256, 2), 256>>>(
        xr_[0], xr_[1], convW[0], convW[1], convB[0], convB[1], xsc_[0], xsc_[1]);

    // 4) x_proj -> [dlt | B | C], both dirs
    mma_gemm<<<dim3(BL / 128, 1, 2), 256, SMEM_BYTES>>>(
        xsc_[0], xsc_[1], DI, 0,
        xW[0], xW[1], XDBLC,
        xdbl_[0], xdbl_[1], XDBLC, 0, 0,
        XDBLC, DI, 0, nullptr, nullptr, nullptr);

    // 5) chunked scan (delta fused): local -> combine -> correct+gate
    scanA_kernel<<<dim3(DI / 128, NCH, 16), 128>>>(
        xdbl_[0], xdbl_[1], xsc_[0], xsc_[1],
        dtW[0], dtW[1], dtB[0], dtB[1],
        ALog[0], ALog[1], y_[0], y_[1], hfin, dSb);
    scanB_kernel<<<32, 256>>>(hfin, dSb, ALog[0], ALog[1]);
    scanC_kernel<<<dim3(DI / 128, NCH, 16), 128>>>(
        xdbl_[0], xdbl_[1], xsc_[0], xsc_[1], xr_[0], xr_[1],
        dtW[0], dtW[1], dtB[0], dtB[1],
        ALog[0], ALog[1], Dp[0], Dp[1], y_[0], y_[1], hfin);

    // 6) combined out_proj + fuse + residual (dual-A, K=1024):
    //    out[m] = x[m] + fusB + y_f[m] @ Cf + y_b[m^1023] @ Cb
    mma_gemm<<<dim3(BL / 128, 2, 1), 256, SMEM_BYTES>>>(
        y_[0], y_[1], DI, 2,
        Wcomb, Wcomb, DM,
        out, out, DM, 0, 0,
        DM, 1024, 2, fusB, fusB, x);
}

// round 7
// speedup vs baseline: 1.3440x; 1.1329x over previous
#include <cuda_runtime.h>
#include <cuda_bf16.h>
#include <cstdint>

typedef __nv_bfloat16 BF;

#define BATCH 8
#define LSEQ  1024
#define DM    256
#define DS    16
#define DC    4
#define DI    512
#define DTR   16
#define BL    (BATCH * LSEQ)   // 8192
#define XDBLC (DTR + 2 * DS)   // 48
#define CH    128
#define NCH   (LSEQ / CH)      // 8

// ---------------- scratch (floats; bf16 arrays carved by cast) -------------
static const size_t OFF_XNH   = 0;                                     // bf16 BL*DM
static const size_t OFF_XR    = OFF_XNH  + (size_t)BL * DM / 2;
static const size_t OFF_XSC   = OFF_XR   + (size_t)2 * BL * 2 * DI;
static const size_t OFF_XSCH  = OFF_XSC  + (size_t)2 * BL * DI;        // bf16
static const size_t OFF_XDBL  = OFF_XSCH + (size_t)2 * BL * DI / 2;
static const size_t OFF_Y     = OFF_XDBL + (size_t)2 * BL * XDBLC;
static const size_t OFF_YH    = OFF_Y    + (size_t)2 * BL * DI;        // bf16
static const size_t OFF_WTIN  = OFF_YH   + (size_t)2 * BL * DI / 2;    // bf16 2*1024*256
static const size_t OFF_WTX   = OFF_WTIN + (size_t)2 * 1024 * 256 / 2; // bf16 2*48*512
static const size_t OFF_FWT   = OFF_WTX  + (size_t)2 * 48 * 512 / 2;   // bf16 256*512
static const size_t OFF_OWH   = OFF_FWT  + (size_t)256 * 512 / 2;      // bf16 2*512*256
static const size_t OFF_WCT   = OFF_OWH  + (size_t)2 * 512 * 256 / 2;  // bf16 256*1024
static const size_t OFF_HF    = OFF_WCT  + (size_t)256 * 1024 / 2;
static const size_t OFF_DS    = OFF_HF   + (size_t)2 * 8 * NCH * 16 * 512;
static const size_t TOTAL_F   = OFF_DS   + (size_t)2 * 8 * NCH * 512;

__device__ float g_buf[TOTAL_F];

// ---------------- weight prep: transpose+convert / convert -----------------
__global__ void transpose_convert(const float* __restrict__ src, BF* __restrict__ dst,
                                  int R, int Cc)
{
    __shared__ float tile[32][33];
    int c0 = blockIdx.x * 32, r0 = blockIdx.y * 32;
    int tx = threadIdx.x & 31, ty = threadIdx.x >> 5;   // 256 thr: 32x8
    #pragma unroll
    for (int i = ty; i < 32; i += 8) {
        int r = r0 + i, c = c0 + tx;
        tile[i][tx] = (r < R && c < Cc) ? src[(size_t)r * Cc + c] : 0.f;
    }
    __syncthreads();
    #pragma unroll
    for (int i = ty; i < 32; i += 8) {
        int c = c0 + i, r = r0 + tx;
        if (c < Cc && r < R) dst[(size_t)c * R + r] = __float2bfloat16(tile[tx][i]);
    }
}

__global__ void convert_bf16(const float* __restrict__ s0, const float* __restrict__ s1,
                             BF* __restrict__ d0, BF* __restrict__ d1, int n)
{
    const float* s = blockIdx.y ? s1 : s0;
    BF* d = blockIdx.y ? d1 : d0;
    int i = blockIdx.x * 256 + threadIdx.x;
    if (i < n) d[i] = __float2bfloat16(s[i]);
}

// ---------------- LayerNorm: warp per token, writes bf16 -------------------
__global__ __launch_bounds__(256)
void ln_kernel(const float* __restrict__ x,
               const float* __restrict__ g,
               const float* __restrict__ b,
               BF* __restrict__ xn)
{
    int warp = threadIdx.x >> 5, lane = threadIdx.x & 31;
    int tok = blockIdx.x * 8 + warp;
    const float4* xp = (const float4*)(x + (size_t)tok * DM) + lane * 2;
    float4 u0 = xp[0], u1 = xp[1];
    float s  = u0.x + u0.y + u0.z + u0.w + u1.x + u1.y + u1.z + u1.w;
    float s2 = u0.x*u0.x + u0.y*u0.y + u0.z*u0.z + u0.w*u0.w
             + u1.x*u1.x + u1.y*u1.y + u1.z*u1.z + u1.w*u1.w;
    #pragma unroll
    for (int o = 16; o; o >>= 1) {
        s  += __shfl_xor_sync(0xffffffffu, s,  o);
        s2 += __shfl_xor_sync(0xffffffffu, s2, o);
    }
    float mu  = s * (1.0f / DM);
    float var = s2 * (1.0f / DM) - mu * mu;
    float r = rsqrtf(var + 1e-5f);
    const float4* gp = (const float4*)g + lane * 2;
    const float4* bp = (const float4*)b + lane * 2;
    float4 g0 = gp[0], g1 = gp[1], b0 = bp[0], b1 = bp[1];
    float o_[8];
    o_[0] = (u0.x - mu) * r * g0.x + b0.x;  o_[1] = (u0.y - mu) * r * g0.y + b0.y;
    o_[2] = (u0.z - mu) * r * g0.z + b0.z;  o_[3] = (u0.w - mu) * r * g0.w + b0.w;
    o_[4] = (u1.x - mu) * r * g1.x + b1.x;  o_[5] = (u1.y - mu) * r * g1.y + b1.y;
    o_[6] = (u1.z - mu) * r * g1.z + b1.z;  o_[7] = (u1.w - mu) * r * g1.w + b1.w;
    __nv_bfloat162 h[4];
    #pragma unroll
    for (int i = 0; i < 4; i++) h[i] = __floats2bfloat162_rn(o_[2*i], o_[2*i+1]);
    *(uint4*)(xn + (size_t)tok * DM + lane * 8) = *(uint4*)h;
}

// ---------------- bf16 tensor-core GEMM ------------------------------------
// C[r, coff+c] = sum_k A[amap(r), k] * Bt[c, k]   (both K-major bf16)
// 128x128x32 tiles, 3-stage cp.async ring, 256 threads (8 warps 2x4),
// warp tile 64x32, mma m16n8k16, all fragments via ldmatrix.x4.
// flipMode: 0 none; 1 flip A rows (m^1023) when z==1; 2 dual-A (K split 512).
// epi: 0 f32 store; 2 f32 store + bias[c] + resid[r*N+c]; 3 bf16 store.

#define SA 40
#define STAGES 3
#define SMEM_BYTES (STAGES * 2 * 128 * SA * 2)

__device__ __forceinline__ unsigned cvta_s(const void* p) {
    return (unsigned)__cvta_generic_to_shared(p);
}
__device__ __forceinline__ void cp16(unsigned dst, const void* src, int srcbytes) {
    asm volatile("cp.async.cg.shared.global [%0], [%1], 16, %2;\n"
                 :: "r"(dst), "l"(src), "r"(srcbytes));
}

__global__ __launch_bounds__(256)
void mma_gemm(const BF* __restrict__ A0, const BF* __restrict__ A1, int lda, int flipMode,
              const BF* __restrict__ W0, const BF* __restrict__ W1, int ldw,
              float* __restrict__ C0, float* __restrict__ C1, int ldc, int coffz,
              int N, int K, int epi,
              const float* __restrict__ bias0, const float* __restrict__ bias1,
              const float* __restrict__ resid)
{
    extern __shared__ BF smem[];
    BF* As = smem;                            // [STAGES][128][SA]
    BF* Bs = smem + STAGES * 128 * SA;        // [STAGES][128][SA]

    const int z = blockIdx.z;
    const BF* A = z ? A1 : A0;
    const BF* W = z ? W1 : W0;
    float*    C = z ? C1 : C0;
    const float* bias = z ? bias1 : bias0;
    const bool dual = (flipMode == 2);
    const int fA = (flipMode == 1 && z);
    const int coff = coffz * z;

    const int tid = threadIdx.x;
    const int m0 = blockIdx.x * 128;
    const int n0 = blockIdx.y * 128;

    const int ar  = tid >> 1;           // row 0..127
    const int akc = (tid & 1) * 16;     // bf16 col 0 or 16
    int gm = m0 + ar;
    if (fA) gm ^= (LSEQ - 1);
    const BF* A0row = A + (size_t)gm * lda;
    const BF* A1row = dual ? (A1 + (size_t)(gm ^ (LSEQ - 1)) * lda) : A;
    int nr = n0 + ar;
    const BF* Brow = W + (size_t)(nr < N ? nr : 0) * ldw;
    const bool bok = (nr < N);

    const int wid = tid >> 5, lane = tid & 31;
    const int wm = wid & 1, wn = wid >> 1;
    const int lr = lane >> 2, lc = lane & 3;
    const int a_row = (lane & 15);
    const int a_kof = (lane >> 4) * 8;
    const int b_row = (lane & 7) + ((lane & 16) ? 8 : 0);
    const int b_kof = (lane & 8) ? 8 : 0;

    float acc[4][4][4];
    #pragma unroll
    for (int mi = 0; mi < 4; mi++)
        #pragma unroll
        for (int ni = 0; ni < 4; ni++)
            #pragma unroll
            for (int q = 0; q < 4; q++) acc[mi][ni][q] = 0.f;

    const int nk = K >> 5;   // K always multiple of 32 here

    auto loadA = [&](int kk, int buf) {
        BF* dst = As + buf * (128 * SA) + ar * SA + akc;
        #pragma unroll
        for (int j = 0; j < 2; j++) {
            int kg = kk + akc + j * 8;
            const BF* src = (dual && kg >= 512) ? (A1row + kg - 512) : (A0row + kg);
            cp16(cvta_s(dst + j * 8), src, 16);
        }
    };
    auto loadB = [&](int kk, int buf) {
        BF* dst = Bs + buf * (128 * SA) + ar * SA + akc;
        #pragma unroll
        for (int j = 0; j < 2; j++) {
            int kg = kk + akc + j * 8;
            cp16(cvta_s(dst + j * 8), Brow + kg, bok ? 16 : 0);
        }
    };

    loadA(0, 0); loadB(0, 0);
    asm volatile("cp.async.commit_group;\n");
    loadA(32, 1); loadB(32, 1);
    asm volatile("cp.async.commit_group;\n");

    int buf = 0;
    for (int t = 0; t < nk; t++) {
        asm volatile("cp.async.wait_group %0;\n" :: "n"(STAGES - 2));
        __syncthreads();

        if (t + STAGES - 1 < nk) {
            int nb = buf + (STAGES - 1); if (nb >= STAGES) nb -= STAGES;
            loadA((t + STAGES - 1) << 5, nb);
            loadB((t + STAGES - 1) << 5, nb);
        }
        asm volatile("cp.async.commit_group;\n");

        unsigned AsAddr = cvta_s(As + buf * (128 * SA));
        unsigned BsAddr = cvta_s(Bs + buf * (128 * SA));

        #pragma unroll
        for (int s = 0; s < 2; s++) {
            unsigned af[4][4], br[2][4];
            #pragma unroll
            for (int mi = 0; mi < 4; mi++) {
                unsigned a_addr = AsAddr +
                    (unsigned)(((wm * 64 + mi * 16 + a_row) * SA + s * 16 + a_kof) * 2);
                asm volatile(
                    "ldmatrix.sync.aligned.m8n8.x4.shared.b16 {%0,%1,%2,%3}, [%4];\n"
                    : "=r"(af[mi][0]), "=r"(af[mi][1]), "=r"(af[mi][2]), "=r"(af[mi][3])
                    : "r"(a_addr));
            }
            #pragma unroll
            for (int p = 0; p < 2; p++) {
                unsigned b_addr = BsAddr +
                    (unsigned)(((wn * 32 + p * 16 + b_row) * SA + s * 16 + b_kof) * 2);
                asm volatile(
                    "ldmatrix.sync.aligned.m8n8.x4.shared.b16 {%0,%1,%2,%3}, [%4];\n"
                    : "=r"(br[p][0]), "=r"(br[p][1]), "=r"(br[p][2]), "=r"(br[p][3])
                    : "r"(b_addr));
            }
            #pragma unroll
            for (int mi = 0; mi < 4; mi++)
                #pragma unroll
                for (int ni = 0; ni < 4; ni++) {
                    unsigned b0 = br[ni >> 1][(ni & 1) * 2];
                    unsigned b1 = br[ni >> 1][(ni & 1) * 2 + 1];
                    asm volatile(
                        "mma.sync.aligned.m16n8k16.row.col.f32.bf16.bf16.f32 "
                        "{%0,%1,%2,%3},{%4,%5,%6,%7},{%8,%9},{%0,%1,%2,%3};\n"
                        : "+f"(acc[mi][ni][0]), "+f"(acc[mi][ni][1]),
                          "+f"(acc[mi][ni][2]), "+f"(acc[mi][ni][3])
                        : "r"(af[mi][0]), "r"(af[mi][1]), "r"(af[mi][2]), "r"(af[mi][3]),
                          "r"(b0), "r"(b1));
                }
        }
        buf++; if (buf >= STAGES) buf = 0;
    }

    #pragma unroll
    for (int mi = 0; mi < 4; mi++) {
        int r0r = m0 + wm * 64 + mi * 16 + lr;
        #pragma unroll
        for (int ni = 0; ni < 4; ni++) {
            int cb = n0 + wn * 32 + ni * 8 + 2 * lc;
            #pragma unroll
            for (int q = 0; q < 4; q++) {
                int r = r0r + (q >> 1) * 8;
                int c = cb + (q & 1);
                if (c < N) {
                    float v = acc[mi][ni][q];
                    if (epi == 2)
                        v += bias[c] + resid[(size_t)r * N + c];
                    if (epi == 3)
                        ((BF*)C)[(size_t)r * ldc + coff + c] = __float2bfloat16(v);
                    else
                        C[(size_t)r * ldc + coff + c] = v;
                }
            }
        }
    }
}

// ---------------- causal depthwise conv + bias + SiLU (f32 + bf16 out) -----
__global__ __launch_bounds__(256)
void conv_silu_kernel(const float* __restrict__ xr0, const float* __restrict__ xr1,
                      const float* __restrict__ cw0, const float* __restrict__ cw1,
                      const float* __restrict__ cb0, const float* __restrict__ cb1,
                      float* __restrict__ xsc0, float* __restrict__ xsc1,
                      BF* __restrict__ xh0, BF* __restrict__ xh1)
{
    int dir = blockIdx.y;
    const float* xr = dir ? xr1 : xr0;
    const float* cw = dir ? cw1 : cw0;
    const float* cb = dir ? cb1 : cb0;
    float* xsc = dir ? xsc1 : xsc0;
    BF* xh = dir ? xh1 : xh0;

    int idx = blockIdx.x * 256 + threadIdx.x;
    int c   = idx & (DI - 1);
    int rb  = idx >> 9;
    int t0  = rb * 4;
    int tau0 = t0 & (LSEQ - 1);

    const float* p = xr + (size_t)t0 * (2 * DI) + c;
    float w0 = cw[c * 4 + 0], w1 = cw[c * 4 + 1], w2 = cw[c * 4 + 2], w3 = cw[c * 4 + 3];
    float bias = cb[c];

    float v[7];
    #pragma unroll
    for (int j = 0; j < 7; j++) {
        int off = j - 3;
        bool valid = (tau0 + off >= 0);
        v[j] = valid ? p[(long)off * 2 * DI] : 0.f;
    }
    float* op = xsc + (size_t)t0 * DI + c;
    BF* oh = xh + (size_t)t0 * DI + c;
    #pragma unroll
    for (int k = 0; k < 4; k++) {
        float acc = bias;
        acc = fmaf(v[k],     w0, acc);
        acc = fmaf(v[k + 1], w1, acc);
        acc = fmaf(v[k + 2], w2, acc);
        acc = fmaf(v[k + 3], w3, acc);
        float sv = acc / (1.f + __expf(-acc));
        op[(size_t)k * DI] = sv;
        oh[(size_t)k * DI] = __float2bfloat16(sv);
    }
}

// ---------------- chunked selective scan (delta fused in) -------------------
__device__ __forceinline__ void powers16(float q, float* p) {
    p[0] = q;        p[1] = q * q;     p[2] = p[1] * q;   p[3] = p[1] * p[1];
    p[4] = p[3] * q; p[5] = p[3] * p[1]; p[6] = p[3] * p[2]; p[7] = p[3] * p[3];
    p[8]  = p[7] * q;    p[9]  = p[7] * p[1]; p[10] = p[7] * p[2]; p[11] = p[7] * p[3];
    p[12] = p[7] * p[4]; p[13] = p[7] * p[5]; p[14] = p[7] * p[6]; p[15] = p[7] * p[7];
}

__device__ __forceinline__ bool load_a(const float* __restrict__ ALog, int d, float* a) {
    #pragma unroll
    for (int n = 0; n < 16; n++) a[n] = -__expf(ALog[d * 16 + n]);
    bool fast = true;
    float a1 = a[0];
    #pragma unroll
    for (int n = 1; n < 16; n++)
        fast = fast && (fabsf(a[n] - (n + 1) * a1) <= 1e-4f * fabsf((n + 1) * a1));
    return fast;
}

__device__ __forceinline__ float softplus_f(float v) {
    return (v > 20.f) ? v : log1pf(__expf(v));
}

__global__ __launch_bounds__(128)
void scanA_kernel(const float* __restrict__ xdbl0, const float* __restrict__ xdbl1,
                  const float* __restrict__ xsc0, const float* __restrict__ xsc1,
                  const float* __restrict__ dtW0, const float* __restrict__ dtW1,
                  const float* __restrict__ dtB0, const float* __restrict__ dtB1,
                  const float* __restrict__ ALog0, const float* __restrict__ ALog1,
                  float* __restrict__ y0, float* __restrict__ y1,
                  float* __restrict__ hfin, float* __restrict__ dSb)
{
    int zb  = blockIdx.z;
    int dir = zb >> 3;
    const float* xdbl = dir ? xdbl1 : xdbl0;
    const float* xsc  = dir ? xsc1  : xsc0;
    const float* dtW  = dir ? dtW1  : dtW0;
    const float* dtB  = dir ? dtB1  : dtB0;
    const float* ALog = dir ? ALog1 : ALog0;
    float* y          = dir ? y1    : y0;

    int ch  = blockIdx.y;
    int tid = threadIdx.x;
    int d   = blockIdx.x * 128 + tid;
    int b   = zb & 7;
    int base = b * LSEQ + ch * CH;

    __shared__ float sX[CH][XDBLC];
    for (int i = tid; i < CH * 12; i += 128) {
        int tt = i / 12, q = i % 12;
        *(float4*)&sX[tt][q * 4] =
            *(const float4*)&xdbl[(size_t)(base + tt) * XDBLC + q * 4];
    }
    __syncthreads();

    float wreg[16];
    #pragma unroll
    for (int j = 0; j < 16; j++) wreg[j] = dtW[j * DI + d];
    float dbias = dtB[d];

    float a[16];
    bool fast = load_a(ALog, d, a);
    float a1 = a[0];

    float h[16];
    #pragma unroll
    for (int n = 0; n < 16; n++) h[n] = 0.f;
    float S = 0.f;

    const float* xp = xsc + (size_t)base * DI + d;
    float* yp       = y   + (size_t)base * DI + d;

    if (fast) {
        #pragma unroll 2
        for (int t = 0; t < CH; t++) {
            float raw = dbias;
            #pragma unroll
            for (int j = 0; j < 16; j++) raw = fmaf(wreg[j], sX[t][j], raw);
            float dlt = softplus_f(raw);
            float xv  = xp[(size_t)t * DI];
            S += dlt;
            float dx = dlt * xv;
            float p[16];
            powers16(__expf(dlt * a1), p);
            float yv = 0.f;
            #pragma unroll
            for (int n = 0; n < 16; n++) {
                h[n] = fmaf(p[n], h[n], dx * sX[t][16 + n]);
                yv   = fmaf(h[n], sX[t][32 + n], yv);
            }
            yp[(size_t)t * DI] = yv;
        }
    } else {
        for (int t = 0; t < CH; t++) {
            float raw = dbias;
            #pragma unroll
            for (int j = 0; j < 16; j++) raw = fmaf(wreg[j], sX[t][j], raw);
            float dlt = softplus_f(raw);
            float xv  = xp[(size_t)t * DI];
            S += dlt;
            float dx = dlt * xv;
            float yv = 0.f;
            #pragma unroll
            for (int n = 0; n < 16; n++) {
                float dA = __expf(dlt * a[n]);
                h[n] = fmaf(dA, h[n], dx * sX[t][16 + n]);
                yv   = fmaf(h[n], sX[t][32 + n], yv);
            }
            yp[(size_t)t * DI] = yv;
        }
    }

    size_t cc = (size_t)(zb * NCH + ch);
    #pragma unroll
    for (int n = 0; n < 16; n++) hfin[cc * 8192 + n * 512 + d] = h[n];
    dSb[cc * 512 + d] = S;
}

__global__ void scanB_kernel(float* __restrict__ hfin, const float* __restrict__ dSb,
                             const float* __restrict__ ALog0, const float* __restrict__ ALog1)
{
    int idx = blockIdx.x * 256 + threadIdx.x;
    int d  = idx & 511;
    int zb = idx >> 9;
    const float* ALog = (zb >> 3) ? ALog1 : ALog0;

    float a[16];
    bool fast = load_a(ALog, d, a);
    float a1 = a[0];

    float hin[16];
    #pragma unroll
    for (int n = 0; n < 16; n++) hin[n] = 0.f;

    for (int c = 0; c < NCH; c++) {
        size_t cc = (size_t)(zb * NCH + c);
        float S = dSb[cc * 512 + d];
        float P[16];
        if (fast) {
            powers16(__expf(S * a1), P);
        } else {
            #pragma unroll
            for (int n = 0; n < 16; n++) P[n] = __expf(S * a[n]);
        }
        #pragma unroll
        for (int n = 0; n < 16; n++) {
            float hf = hfin[cc * 8192 + n * 512 + d];
            hfin[cc * 8192 + n * 512 + d] = hin[n];
            hin[n] = fmaf(P[n], hin[n], hf);
        }
    }
}

// Phase C: correction + D*x + silu(res) gate; writes bf16 y_h.
__global__ __launch_bounds__(128)
void scanC_kernel(const float* __restrict__ xdbl0, const float* __restrict__ xdbl1,
                  const float* __restrict__ xsc0, const float* __restrict__ xsc1,
                  const float* __restrict__ xr0, const float* __restrict__ xr1,
                  const float* __restrict__ dtW0, const float* __restrict__ dtW1,
                  const float* __restrict__ dtB0, const float* __restrict__ dtB1,
                  const float* __restrict__ ALog0, const float* __restrict__ ALog1,
                  const float* __restrict__ Dp0, const float* __restrict__ Dp1,
                  const float* __restrict__ y0, const float* __restrict__ y1,
                  BF* __restrict__ yh0, BF* __restrict__ yh1,
                  const float* __restrict__ hfin)
{
    int zb  = blockIdx.z;
    int dir = zb >> 3;
    const float* xdbl = dir ? xdbl1 : xdbl0;
    const float* xsc  = dir ? xsc1  : xsc0;
    const float* xr   = dir ? xr1   : xr0;
    const float* dtW  = dir ? dtW1  : dtW0;
    const float* dtB  = dir ? dtB1  : dtB0;
    const float* ALog = dir ? ALog1 : ALog0;
    const float* Dp   = dir ? Dp1   : Dp0;
    const float* y    = dir ? y1    : y0;
    BF* yh            = dir ? yh1   : yh0;

    int ch  = blockIdx.y;
    int tid = threadIdx.x;
    int d   = blockIdx.x * 128 + tid;
    int b   = zb & 7;
    int base = b * LSEQ + ch * CH;

    __shared__ float sX[CH][XDBLC];
    for (int i = tid; i < CH * 12; i += 128) {
        int tt = i / 12, q = i % 12;
        *(float4*)&sX[tt][q * 4] =
            *(const float4*)&xdbl[(size_t)(base + tt) * XDBLC + q * 4];
    }
    __syncthreads();

    float a[16];
    bool fast = load_a(ALog, d, a);
    float a1 = a[0];
    float Dv = Dp[d];

    size_t cc = (size_t)(zb * NCH + ch);
    float w[16];
    bool zero = true;
    #pragma unroll
    for (int n = 0; n < 16; n++) {
        w[n] = hfin[cc * 8192 + n * 512 + d];
        zero = zero && (w[n] == 0.f);
    }

    const float* xp = xsc + (size_t)base * DI + d;
    const float* rp = xr  + (size_t)base * (2 * DI) + DI + d;
    const float* yp = y   + (size_t)base * DI + d;
    BF* yhp         = yh  + (size_t)base * DI + d;

    if (zero) {
        #pragma unroll 4
        for (int t = 0; t < CH; t++) {
            float xv  = xp[(size_t)t * DI];
            float res = rp[(size_t)t * (2 * DI)];
            float yl  = yp[(size_t)t * DI];
            float sres = res / (1.f + __expf(-res));
            yhp[(size_t)t * DI] = __float2bfloat16((yl + Dv * xv) * sres);
        }
        return;
    }

    float wreg[16];
    #pragma unroll
    for (int j = 0; j < 16; j++) wreg[j] = dtW[j * DI + d];
    float dbias = dtB[d];

    if (fast) {
        float r = 1.f;
        #pragma unroll 2
        for (int t = 0; t < CH; t++) {
            float raw = dbias;
            #pragma unroll
            for (int j = 0; j < 16; j++) raw = fmaf(wreg[j], sX[t][j], raw);
            float dlt = softplus_f(raw);
            float xv  = xp[(size_t)t * DI];
            float res = rp[(size_t)t * (2 * DI)];
            float yl  = yp[(size_t)t * DI];
            r *= __expf(dlt * a1);
            float p[16];
            powers16(r, p);
            float corr = 0.f;
            #pragma unroll
            for (int n = 0; n < 16; n++)
                corr = fmaf(w[n] * p[n], sX[t][32 + n], corr);
            float sres = res / (1.f + __expf(-res));
            yhp[(size_t)t * DI] = __float2bfloat16((yl + corr + Dv * xv) * sres);
        }
    } else {
        float S = 0.f;
        for (int t = 0; t < CH; t++) {
            float raw = dbias;
            #pragma unroll
            for (int j = 0; j < 16; j++) raw = fmaf(wreg[j], sX[t][j], raw);
            float dlt = softplus_f(raw);
            float xv  = xp[(size_t)t * DI];
            float res = rp[(size_t)t * (2 * DI)];
            float yl  = yp[(size_t)t * DI];
            S += dlt;
            float corr = 0.f;
            #pragma unroll
            for (int n = 0; n < 16; n++)
                corr = fmaf(w[n] * __expf(S * a[n]), sX[t][32 + n], corr);
            float sres = res / (1.f + __expf(-res));
            yhp[(size_t)t * DI] = __float2bfloat16((yl + corr + Dv * xv) * sres);
        }
    }
}

// ---------------- launcher -------------------------------------------------
extern "C" void kernel_launch(void* const* d_in, const int* in_sizes, int n_in,
                              void* d_out, int out_size)
{
    const float* x      = (const float*)d_in[0];
    const float* norm_g = (const float*)d_in[1];
    const float* norm_b = (const float*)d_in[2];
    const float* inW[2]   = {(const float*)d_in[3],  (const float*)d_in[12]};
    const float* convW[2] = {(const float*)d_in[4],  (const float*)d_in[13]};
    const float* convB[2] = {(const float*)d_in[5],  (const float*)d_in[14]};
    const float* xW[2]    = {(const float*)d_in[6],  (const float*)d_in[15]};
    const float* dtW[2]   = {(const float*)d_in[7],  (const float*)d_in[16]};
    const float* dtB[2]   = {(const float*)d_in[8],  (const float*)d_in[17]};
    const float* ALog[2]  = {(const float*)d_in[9],  (const float*)d_in[18]};
    const float* Dp[2]    = {(const float*)d_in[10], (const float*)d_in[19]};
    const float* outW[2]  = {(const float*)d_in[11], (const float*)d_in[20]};
    const float* fusW = (const float*)d_in[21];
    const float* fusB = (const float*)d_in[22];
    float* out = (float*)d_out;

    float* base = nullptr;
    cudaGetSymbolAddress((void**)&base, g_buf);
    BF*    xn_h      = (BF*)(base + OFF_XNH);
    float* xr_[2]    = {base + OFF_XR,   base + OFF_XR   + (size_t)BL * 2 * DI};
    float* xsc_[2]   = {base + OFF_XSC,  base + OFF_XSC  + (size_t)BL * DI};
    BF*    xsch_[2]  = {(BF*)(base + OFF_XSCH), (BF*)(base + OFF_XSCH) + (size_t)BL * DI};
    float* xdbl_[2]  = {base + OFF_XDBL, base + OFF_XDBL + (size_t)BL * XDBLC};
    float* y_[2]     = {base + OFF_Y,    base + OFF_Y    + (size_t)BL * DI};
    BF*    yh_[2]    = {(BF*)(base + OFF_YH), (BF*)(base + OFF_YH) + (size_t)BL * DI};
    BF*    WtIn[2]   = {(BF*)(base + OFF_WTIN), (BF*)(base + OFF_WTIN) + (size_t)1024 * 256};
    BF*    WtX[2]    = {(BF*)(base + OFF_WTX),  (BF*)(base + OFF_WTX)  + (size_t)48 * 512};
    BF*    fusWt     = (BF*)(base + OFF_FWT);
    BF*    outWh[2]  = {(BF*)(base + OFF_OWH), (BF*)(base + OFF_OWH) + (size_t)512 * 256};
    BF*    WcombT    = (BF*)(base + OFF_WCT);
    float* hfin      = base + OFF_HF;
    float* dSb       = base + OFF_DS;

    static bool attr_set = false;
    if (!attr_set) {
        cudaFuncSetAttribute(mma_gemm, cudaFuncAttributeMaxDynamicSharedMemorySize, SMEM_BYTES);
        attr_set = true;
    }

    // 0) weight prep
    transpose_convert<<<dim3(32, 8), 256>>>(inW[0], WtIn[0], 256, 1024);
    transpose_convert<<<dim3(32, 8), 256>>>(inW[1], WtIn[1], 256, 1024);
    transpose_convert<<<dim3(2, 16), 256>>>(xW[0], WtX[0], 512, 48);
    transpose_convert<<<dim3(2, 16), 256>>>(xW[1], WtX[1], 512, 48);
    transpose_convert<<<dim3(8, 16), 256>>>(fusW, fusWt, 512, 256);
    convert_bf16<<<dim3(512, 2), 256>>>(outW[0], outW[1], outWh[0], outWh[1], 512 * 256);

    // 0b) WcombT[n, k + z*512] = sum_j fusWt[n, z*256+j] * outWh_z[k, j]  (bf16 out)
    mma_gemm<<<dim3(2, 4, 2), 256, SMEM_BYTES>>>(
        fusWt, fusWt + 256, 512, 0,
        outWh[0], outWh[1], 256,
        (float*)WcombT, (float*)WcombT, 1024, 512,
        512, 256, 3, nullptr, nullptr, nullptr);

    // 1) LayerNorm -> bf16
    ln_kernel<<<BL / 8, 256>>>(x, norm_g, norm_b, xn_h);

    // 2) in_proj, both dirs (flip A rows for backward)
    mma_gemm<<<dim3(BL / 128, 8, 2), 256, SMEM_BYTES>>>(
        xn_h, xn_h, DM, 1,
        WtIn[0], WtIn[1], 256,
        xr_[0], xr_[1], 2 * DI, 0,
        2 * DI, DM, 0, nullptr, nullptr, nullptr);

    // 3) causal dw-conv + silu -> f32 + bf16
    conv_silu_kernel<<<dim3((BL / 4) * DI / 256, 2), 256>>>(
        xr_[0], xr_[1], convW[0], convW[1], convB[0], convB[1],
        xsc_[0], xsc_[1], xsch_[0], xsch_[1]);

    // 4) x_proj -> [dlt | B | C]
    mma_gemm<<<dim3(BL / 128, 1, 2), 256, SMEM_BYTES>>>(
        xsch_[0], xsch_[1], DI, 0,
        WtX[0], WtX[1], 512,
        xdbl_[0], xdbl_[1], XDBLC, 0,
        XDBLC, DI, 0, nullptr, nullptr, nullptr);

    // 5) chunked scan (delta fused): local -> combine -> correct+gate(bf16)
    scanA_kernel<<<dim3(DI / 128, NCH, 16), 128>>>(
        xdbl_[0], xdbl_[1], xsc_[0], xsc_[1],
        dtW[0], dtW[1], dtB[0], dtB[1],
        ALog[0], ALog[1], y_[0], y_[1], hfin, dSb);
    scanB_kernel<<<32, 256>>>(hfin, dSb, ALog[0], ALog[1]);
    scanC_kernel<<<dim3(DI / 128, NCH, 16), 128>>>(
        xdbl_[0], xdbl_[1], xsc_[0], xsc_[1], xr_[0], xr_[1],
        dtW[0], dtW[1], dtB[0], dtB[1],
        ALog[0], ALog[1], Dp[0], Dp[1], y_[0], y_[1], yh_[0], yh_[1], hfin);

    // 6) combined out_proj + fuse + residual (dual-A, K=1024):
    //    out[m] = x[m] + fusB + y_f[m] @ Cf + y_b[m^1023] @ Cb
    mma_gemm<<<dim3(BL / 128, 2, 1), 256, SMEM_BYTES>>>(
        yh_[0], yh_[1], DI, 2,
        WcombT, WcombT, 1024,
        out, out, DM, 0,
        DM, 1024, 2, fusB, fusB, x);
}

// round 8
// speedup vs baseline: 1.6305x; 1.2132x over previous
#include <cuda_runtime.h>
#include <cuda_bf16.h>
#include <cstdint>

typedef __nv_bfloat16 BF;

#define BATCH 8
#define LSEQ  1024
#define DM    256
#define DS    16
#define DC    4
#define DI    512
#define DTR   16
#define BL    (BATCH * LSEQ)   // 8192
#define XDBLC (DTR + 2 * DS)   // 48
#define CH    128
#define NCH   (LSEQ / CH)      // 8

// ---------------- scratch (float units; bf16 arrays carved by cast) --------
static const size_t OFF_XNH   = 0;                                     // bf16 BL*DM
static const size_t OFF_XRH   = OFF_XNH  + (size_t)BL * DM / 2;        // bf16 2*BL*1024
static const size_t OFF_XSCH  = OFF_XRH  + (size_t)2 * BL * 2 * DI / 2;// bf16 2*BL*DI
static const size_t OFF_XDBL  = OFF_XSCH + (size_t)2 * BL * DI / 2;    // f32  2*BL*48
static const size_t OFF_YB    = OFF_XDBL + (size_t)2 * BL * XDBLC;     // bf16 2*BL*DI
static const size_t OFF_WTIN  = OFF_YB   + (size_t)2 * BL * DI / 2;    // bf16 2*1024*256
static const size_t OFF_WTX   = OFF_WTIN + (size_t)2 * 1024 * 256 / 2; // bf16 2*48*512
static const size_t OFF_FWT   = OFF_WTX  + (size_t)2 * 48 * 512 / 2;   // bf16 256*512
static const size_t OFF_OWH   = OFF_FWT  + (size_t)256 * 512 / 2;      // bf16 2*512*256
static const size_t OFF_WCT   = OFF_OWH  + (size_t)2 * 512 * 256 / 2;  // bf16 256*1024
static const size_t OFF_HF    = OFF_WCT  + (size_t)256 * 1024 / 2;     // f32
static const size_t OFF_DS    = OFF_HF   + (size_t)2 * 8 * NCH * 16 * 512;
static const size_t TOTAL_F   = OFF_DS   + (size_t)2 * 8 * NCH * 512;

__device__ float g_buf[TOTAL_F];

// ---------------- fused prep: all weight transforms + LayerNorm ------------
// blocks [0,960): 32x32 weight tiles (transpose->bf16 or copy->bf16)
// blocks [960,1984): LayerNorm, 8 tokens per block (warp per token)
__global__ __launch_bounds__(256)
void prep_kernel(const float* __restrict__ inW0, const float* __restrict__ inW1,
                 const float* __restrict__ xW0,  const float* __restrict__ xW1,
                 const float* __restrict__ fusW,
                 const float* __restrict__ outW0, const float* __restrict__ outW1,
                 BF* __restrict__ WtIn0, BF* __restrict__ WtIn1,
                 BF* __restrict__ WtX0,  BF* __restrict__ WtX1,
                 BF* __restrict__ fusWt, BF* __restrict__ oW0h, BF* __restrict__ oW1h,
                 const float* __restrict__ x, const float* __restrict__ g,
                 const float* __restrict__ bnorm, BF* __restrict__ xn)
{
    __shared__ float tile[32][33];
    int b = blockIdx.x;
    if (b < 960) {
        const float* src; BF* dst; int R, C, tr, t;
        if (b < 256)      { src = inW0;  dst = WtIn0; R = 256; C = 1024; tr = 1; t = b; }
        else if (b < 512) { src = inW1;  dst = WtIn1; R = 256; C = 1024; tr = 1; t = b - 256; }
        else if (b < 544) { src = xW0;   dst = WtX0;  R = 512; C = 48;   tr = 1; t = b - 512; }
        else if (b < 576) { src = xW1;   dst = WtX1;  R = 512; C = 48;   tr = 1; t = b - 544; }
        else if (b < 704) { src = fusW;  dst = fusWt; R = 512; C = 256;  tr = 1; t = b - 576; }
        else if (b < 832) { src = outW0; dst = oW0h;  R = 512; C = 256;  tr = 0; t = b - 704; }
        else              { src = outW1; dst = oW1h;  R = 512; C = 256;  tr = 0; t = b - 832; }
        int ctiles = (C + 31) >> 5;
        int ct = t % ctiles, rt = t / ctiles;
        int c0 = ct * 32, r0 = rt * 32;
        int tx = threadIdx.x & 31, ty = threadIdx.x >> 5;
        if (tr) {
            #pragma unroll
            for (int i = ty; i < 32; i += 8) {
                int r = r0 + i, c = c0 + tx;
                tile[i][tx] = (r < R && c < C) ? src[(size_t)r * C + c] : 0.f;
            }
            __syncthreads();
            #pragma unroll
            for (int i = ty; i < 32; i += 8) {
                int c = c0 + i, r = r0 + tx;
                if (c < C && r < R) dst[(size_t)c * R + r] = __float2bfloat16(tile[tx][i]);
            }
        } else {
            #pragma unroll
            for (int i = ty; i < 32; i += 8) {
                int r = r0 + i, c = c0 + tx;
                if (r < R && c < C)
                    dst[(size_t)r * C + c] = __float2bfloat16(src[(size_t)r * C + c]);
            }
        }
    } else {
        int warp = threadIdx.x >> 5, lane = threadIdx.x & 31;
        int tok = (b - 960) * 8 + warp;
        const float4* xp = (const float4*)(x + (size_t)tok * DM) + lane * 2;
        float4 u0 = xp[0], u1 = xp[1];
        float s  = u0.x + u0.y + u0.z + u0.w + u1.x + u1.y + u1.z + u1.w;
        float s2 = u0.x*u0.x + u0.y*u0.y + u0.z*u0.z + u0.w*u0.w
                 + u1.x*u1.x + u1.y*u1.y + u1.z*u1.z + u1.w*u1.w;
        #pragma unroll
        for (int o = 16; o; o >>= 1) {
            s  += __shfl_xor_sync(0xffffffffu, s,  o);
            s2 += __shfl_xor_sync(0xffffffffu, s2, o);
        }
        float mu  = s * (1.0f / DM);
        float var = s2 * (1.0f / DM) - mu * mu;
        float r = rsqrtf(var + 1e-5f);
        const float4* gp = (const float4*)g + lane * 2;
        const float4* bp = (const float4*)bnorm + lane * 2;
        float4 g0 = gp[0], g1 = gp[1], b0 = bp[0], b1 = bp[1];
        float o_[8];
        o_[0] = (u0.x - mu) * r * g0.x + b0.x;  o_[1] = (u0.y - mu) * r * g0.y + b0.y;
        o_[2] = (u0.z - mu) * r * g0.z + b0.z;  o_[3] = (u0.w - mu) * r * g0.w + b0.w;
        o_[4] = (u1.x - mu) * r * g1.x + b1.x;  o_[5] = (u1.y - mu) * r * g1.y + b1.y;
        o_[6] = (u1.z - mu) * r * g1.z + b1.z;  o_[7] = (u1.w - mu) * r * g1.w + b1.w;
        __nv_bfloat162 h[4];
        #pragma unroll
        for (int i = 0; i < 4; i++) h[i] = __floats2bfloat162_rn(o_[2*i], o_[2*i+1]);
        *(uint4*)(xn + (size_t)tok * DM + lane * 8) = *(uint4*)h;
    }
}

// ---------------- bf16 tensor-core GEMM ------------------------------------
// C[r, coff+c] = sum_k A[amap(r), k] * Bt[c, k]   (both K-major bf16)
// flipMode: 0 none; 1 flip A rows (m^1023) when z==1; 2 dual-A (K split 512).
// epi: 0 f32 store; 2 f32 + bias[c] + resid[r*N+c]; 3 bf16 store.

#define SA 40
#define STAGES 3
#define SMEM_BYTES (STAGES * 2 * 128 * SA * 2)

__device__ __forceinline__ unsigned cvta_s(const void* p) {
    return (unsigned)__cvta_generic_to_shared(p);
}
__device__ __forceinline__ void cp16(unsigned dst, const void* src, int srcbytes) {
    asm volatile("cp.async.cg.shared.global [%0], [%1], 16, %2;\n"
                 :: "r"(dst), "l"(src), "r"(srcbytes));
}

__global__ __launch_bounds__(256, 2)
void mma_gemm(const BF* __restrict__ A0, const BF* __restrict__ A1, int lda, int flipMode,
              const BF* __restrict__ W0, const BF* __restrict__ W1, int ldw,
              float* __restrict__ C0, float* __restrict__ C1, int ldc, int coffz,
              int N, int K, int epi,
              const float* __restrict__ bias0, const float* __restrict__ bias1,
              const float* __restrict__ resid)
{
    extern __shared__ BF smem[];
    BF* As = smem;
    BF* Bs = smem + STAGES * 128 * SA;

    const int z = blockIdx.z;
    const BF* A = z ? A1 : A0;
    const BF* W = z ? W1 : W0;
    float*    C = z ? C1 : C0;
    const float* bias = z ? bias1 : bias0;
    const bool dual = (flipMode == 2);
    const int fA = (flipMode == 1 && z);
    const int coff = coffz * z;

    const int tid = threadIdx.x;
    const int m0 = blockIdx.x * 128;
    const int n0 = blockIdx.y * 128;

    const int ar  = tid >> 1;
    const int akc = (tid & 1) * 16;
    int gm = m0 + ar;
    if (fA) gm ^= (LSEQ - 1);
    const BF* A0row = A + (size_t)gm * lda;
    const BF* A1row = dual ? (A1 + (size_t)(gm ^ (LSEQ - 1)) * lda) : A;
    int nr = n0 + ar;
    const BF* Brow = W + (size_t)(nr < N ? nr : 0) * ldw;
    const bool bok = (nr < N);

    const int wid = tid >> 5, lane = tid & 31;
    const int wm = wid & 1, wn = wid >> 1;
    const int lr = lane >> 2, lc = lane & 3;
    const int a_row = (lane & 15);
    const int a_kof = (lane >> 4) * 8;
    const int b_row = (lane & 7) + ((lane & 16) ? 8 : 0);
    const int b_kof = (lane & 8) ? 8 : 0;

    float acc[4][4][4];
    #pragma unroll
    for (int mi = 0; mi < 4; mi++)
        #pragma unroll
        for (int ni = 0; ni < 4; ni++)
            #pragma unroll
            for (int q = 0; q < 4; q++) acc[mi][ni][q] = 0.f;

    const int nk = K >> 5;

    auto loadA = [&](int kk, int buf) {
        BF* dst = As + buf * (128 * SA) + ar * SA + akc;
        #pragma unroll
        for (int j = 0; j < 2; j++) {
            int kg = kk + akc + j * 8;
            const BF* src = (dual && kg >= 512) ? (A1row + kg - 512) : (A0row + kg);
            cp16(cvta_s(dst + j * 8), src, 16);
        }
    };
    auto loadB = [&](int kk, int buf) {
        BF* dst = Bs + buf * (128 * SA) + ar * SA + akc;
        #pragma unroll
        for (int j = 0; j < 2; j++) {
            int kg = kk + akc + j * 8;
            cp16(cvta_s(dst + j * 8), Brow + kg, bok ? 16 : 0);
        }
    };

    loadA(0, 0); loadB(0, 0);
    asm volatile("cp.async.commit_group;\n");
    loadA(32, 1); loadB(32, 1);
    asm volatile("cp.async.commit_group;\n");

    int buf = 0;
    for (int t = 0; t < nk; t++) {
        asm volatile("cp.async.wait_group %0;\n" :: "n"(STAGES - 2));
        __syncthreads();

        if (t + STAGES - 1 < nk) {
            int nb = buf + (STAGES - 1); if (nb >= STAGES) nb -= STAGES;
            loadA((t + STAGES - 1) << 5, nb);
            loadB((t + STAGES - 1) << 5, nb);
        }
        asm volatile("cp.async.commit_group;\n");

        unsigned AsAddr = cvta_s(As + buf * (128 * SA));
        unsigned BsAddr = cvta_s(Bs + buf * (128 * SA));

        #pragma unroll
        for (int s = 0; s < 2; s++) {
            unsigned af[4][4], br[2][4];
            #pragma unroll
            for (int mi = 0; mi < 4; mi++) {
                unsigned a_addr = AsAddr +
                    (unsigned)(((wm * 64 + mi * 16 + a_row) * SA + s * 16 + a_kof) * 2);
                asm volatile(
                    "ldmatrix.sync.aligned.m8n8.x4.shared.b16 {%0,%1,%2,%3}, [%4];\n"
                    : "=r"(af[mi][0]), "=r"(af[mi][1]), "=r"(af[mi][2]), "=r"(af[mi][3])
                    : "r"(a_addr));
            }
            #pragma unroll
            for (int p = 0; p < 2; p++) {
                unsigned b_addr = BsAddr +
                    (unsigned)(((wn * 32 + p * 16 + b_row) * SA + s * 16 + b_kof) * 2);
                asm volatile(
                    "ldmatrix.sync.aligned.m8n8.x4.shared.b16 {%0,%1,%2,%3}, [%4];\n"
                    : "=r"(br[p][0]), "=r"(br[p][1]), "=r"(br[p][2]), "=r"(br[p][3])
                    : "r"(b_addr));
            }
            #pragma unroll
            for (int mi = 0; mi < 4; mi++)
                #pragma unroll
                for (int ni = 0; ni < 4; ni++) {
                    unsigned b0 = br[ni >> 1][(ni & 1) * 2];
                    unsigned b1 = br[ni >> 1][(ni & 1) * 2 + 1];
                    asm volatile(
                        "mma.sync.aligned.m16n8k16.row.col.f32.bf16.bf16.f32 "
                        "{%0,%1,%2,%3},{%4,%5,%6,%7},{%8,%9},{%0,%1,%2,%3};\n"
                        : "+f"(acc[mi][ni][0]), "+f"(acc[mi][ni][1]),
                          "+f"(acc[mi][ni][2]), "+f"(acc[mi][ni][3])
                        : "r"(af[mi][0]), "r"(af[mi][1]), "r"(af[mi][2]), "r"(af[mi][3]),
                          "r"(b0), "r"(b1));
                }
        }
        buf++; if (buf >= STAGES) buf = 0;
    }

    #pragma unroll
    for (int mi = 0; mi < 4; mi++) {
        int r0r = m0 + wm * 64 + mi * 16 + lr;
        #pragma unroll
        for (int ni = 0; ni < 4; ni++) {
            int cb = n0 + wn * 32 + ni * 8 + 2 * lc;
            #pragma unroll
            for (int q = 0; q < 4; q++) {
                int r = r0r + (q >> 1) * 8;
                int c = cb + (q & 1);
                if (c < N) {
                    float v = acc[mi][ni][q];
                    if (epi == 2)
                        v += bias[c] + resid[(size_t)r * N + c];
                    if (epi == 3)
                        ((BF*)C)[(size_t)r * ldc + coff + c] = __float2bfloat16(v);
                    else
                        C[(size_t)r * ldc + coff + c] = v;
                }
            }
        }
    }
}

// ---------------- causal depthwise conv + bias + SiLU (bf16 in/out) --------
__global__ __launch_bounds__(256)
void conv_silu_kernel(const BF* __restrict__ xr0, const BF* __restrict__ xr1,
                      const float* __restrict__ cw0, const float* __restrict__ cw1,
                      const float* __restrict__ cb0, const float* __restrict__ cb1,
                      BF* __restrict__ xh0, BF* __restrict__ xh1)
{
    int dir = blockIdx.y;
    const BF* xr = dir ? xr1 : xr0;
    const float* cw = dir ? cw1 : cw0;
    const float* cb = dir ? cb1 : cb0;
    BF* xh = dir ? xh1 : xh0;

    int idx = blockIdx.x * 256 + threadIdx.x;
    int c   = idx & (DI - 1);
    int rb  = idx >> 9;
    int t0  = rb * 4;
    int tau0 = t0 & (LSEQ - 1);

    const BF* p = xr + (size_t)t0 * (2 * DI) + c;
    float w0 = cw[c * 4 + 0], w1 = cw[c * 4 + 1], w2 = cw[c * 4 + 2], w3 = cw[c * 4 + 3];
    float bias = cb[c];

    float v[7];
    #pragma unroll
    for (int j = 0; j < 7; j++) {
        int off = j - 3;
        bool valid = (tau0 + off >= 0);
        v[j] = valid ? __bfloat162float(p[(long)off * 2 * DI]) : 0.f;
    }
    BF* oh = xh + (size_t)t0 * DI + c;
    #pragma unroll
    for (int k = 0; k < 4; k++) {
        float acc = bias;
        acc = fmaf(v[k],     w0, acc);
        acc = fmaf(v[k + 1], w1, acc);
        acc = fmaf(v[k + 2], w2, acc);
        acc = fmaf(v[k + 3], w3, acc);
        oh[(size_t)k * DI] = __float2bfloat16(acc / (1.f + __expf(-acc)));
    }
}

// ---------------- chunked selective scan -----------------------------------
__device__ __forceinline__ void powers16(float q, float* p) {
    p[0] = q;        p[1] = q * q;     p[2] = p[1] * q;   p[3] = p[1] * p[1];
    p[4] = p[3] * q; p[5] = p[3] * p[1]; p[6] = p[3] * p[2]; p[7] = p[3] * p[3];
    p[8]  = p[7] * q;    p[9]  = p[7] * p[1]; p[10] = p[7] * p[2]; p[11] = p[7] * p[3];
    p[12] = p[7] * p[4]; p[13] = p[7] * p[5]; p[14] = p[7] * p[6]; p[15] = p[7] * p[7];
}

__device__ __forceinline__ bool load_a(const float* __restrict__ ALog, int d, float* a) {
    #pragma unroll
    for (int n = 0; n < 16; n++) a[n] = -__expf(ALog[d * 16 + n]);
    bool fast = true;
    float a1 = a[0];
    #pragma unroll
    for (int n = 1; n < 16; n++)
        fast = fast && (fabsf(a[n] - (n + 1) * a1) <= 1e-4f * fabsf((n + 1) * a1));
    return fast;
}

__device__ __forceinline__ float softplus_f(float v) {
    return (v > 20.f) ? v : log1pf(__expf(v));
}

// Phase A: local scan per (dir,b,chunk,d); delta fused; writes bf16 y.
__global__ __launch_bounds__(128)
void scanA_kernel(const float* __restrict__ xdbl0, const float* __restrict__ xdbl1,
                  const BF* __restrict__ xsc0, const BF* __restrict__ xsc1,
                  const float* __restrict__ dtW0, const float* __restrict__ dtW1,
                  const float* __restrict__ dtB0, const float* __restrict__ dtB1,
                  const float* __restrict__ ALog0, const float* __restrict__ ALog1,
                  BF* __restrict__ y0, BF* __restrict__ y1,
                  float* __restrict__ hfin, float* __restrict__ dSb)
{
    int zb  = blockIdx.z;
    int dir = zb >> 3;
    const float* xdbl = dir ? xdbl1 : xdbl0;
    const BF* xsc     = dir ? xsc1  : xsc0;
    const float* dtW  = dir ? dtW1  : dtW0;
    const float* dtB  = dir ? dtB1  : dtB0;
    const float* ALog = dir ? ALog1 : ALog0;
    BF* y             = dir ? y1    : y0;

    int ch  = blockIdx.y;
    int tid = threadIdx.x;
    int d   = blockIdx.x * 128 + tid;
    int b   = zb & 7;
    int base = b * LSEQ + ch * CH;

    __shared__ float sX[CH][XDBLC];
    for (int i = tid; i < CH * 12; i += 128) {
        int tt = i / 12, q = i % 12;
        *(float4*)&sX[tt][q * 4] =
            *(const float4*)&xdbl[(size_t)(base + tt) * XDBLC + q * 4];
    }
    __syncthreads();

    float wreg[16];
    #pragma unroll
    for (int j = 0; j < 16; j++) wreg[j] = dtW[j * DI + d];
    float dbias = dtB[d];

    float a[16];
    bool fast = load_a(ALog, d, a);
    float a1 = a[0];

    float h[16];
    #pragma unroll
    for (int n = 0; n < 16; n++) h[n] = 0.f;
    float S = 0.f;

    const BF* xp = xsc + (size_t)base * DI + d;
    BF* yp       = y   + (size_t)base * DI + d;

    if (fast) {
        #pragma unroll 2
        for (int t = 0; t < CH; t++) {
            float raw = dbias;
            #pragma unroll
            for (int j = 0; j < 16; j++) raw = fmaf(wreg[j], sX[t][j], raw);
            float dlt = softplus_f(raw);
            float xv  = __bfloat162float(xp[(size_t)t * DI]);
            S += dlt;
            float dx = dlt * xv;
            float p[16];
            powers16(__expf(dlt * a1), p);
            float yv = 0.f;
            #pragma unroll
            for (int n = 0; n < 16; n++) {
                h[n] = fmaf(p[n], h[n], dx * sX[t][16 + n]);
                yv   = fmaf(h[n], sX[t][32 + n], yv);
            }
            yp[(size_t)t * DI] = __float2bfloat16(yv);
        }
    } else {
        for (int t = 0; t < CH; t++) {
            float raw = dbias;
            #pragma unroll
            for (int j = 0; j < 16; j++) raw = fmaf(wreg[j], sX[t][j], raw);
            float dlt = softplus_f(raw);
            float xv  = __bfloat162float(xp[(size_t)t * DI]);
            S += dlt;
            float dx = dlt * xv;
            float yv = 0.f;
            #pragma unroll
            for (int n = 0; n < 16; n++) {
                float dA = __expf(dlt * a[n]);
                h[n] = fmaf(dA, h[n], dx * sX[t][16 + n]);
                yv   = fmaf(h[n], sX[t][32 + n], yv);
            }
            yp[(size_t)t * DI] = __float2bfloat16(yv);
        }
    }

    size_t cc = (size_t)(zb * NCH + ch);
    #pragma unroll
    for (int n = 0; n < 16; n++) hfin[cc * 8192 + n * 512 + d] = h[n];
    dSb[cc * 512 + d] = S;
}

// Phase C: per-CTA chunk combine (replaces scanB) + correction + D*x + gate.
// Updates y (bf16) in place.
__global__ __launch_bounds__(128)
void scanC_kernel(const float* __restrict__ xdbl0, const float* __restrict__ xdbl1,
                  const BF* __restrict__ xsc0, const BF* __restrict__ xsc1,
                  const BF* __restrict__ xr0, const BF* __restrict__ xr1,
                  const float* __restrict__ dtW0, const float* __restrict__ dtW1,
                  const float* __restrict__ dtB0, const float* __restrict__ dtB1,
                  const float* __restrict__ ALog0, const float* __restrict__ ALog1,
                  const float* __restrict__ Dp0, const float* __restrict__ Dp1,
                  BF* __restrict__ y0, BF* __restrict__ y1,
                  const float* __restrict__ hfin, const float* __restrict__ dSb)
{
    int zb  = blockIdx.z;
    int dir = zb >> 3;
    const float* xdbl = dir ? xdbl1 : xdbl0;
    const BF* xsc     = dir ? xsc1  : xsc0;
    const BF* xr      = dir ? xr1   : xr0;
    const float* dtW  = dir ? dtW1  : dtW0;
    const float* dtB  = dir ? dtB1  : dtB0;
    const float* ALog = dir ? ALog1 : ALog0;
    const float* Dp   = dir ? Dp1   : Dp0;
    BF* y             = dir ? y1    : y0;

    int ch  = blockIdx.y;
    int tid = threadIdx.x;
    int d   = blockIdx.x * 128 + tid;
    int b   = zb & 7;
    int base = b * LSEQ + ch * CH;

    float a[16];
    bool fast = load_a(ALog, d, a);
    float a1 = a[0];
    float Dv = Dp[d];

    const BF* xp = xsc + (size_t)base * DI + d;
    const BF* rp = xr  + (size_t)base * (2 * DI) + DI + d;
    BF* yp       = y   + (size_t)base * DI + d;

    if (ch == 0) {
        #pragma unroll 4
        for (int t = 0; t < CH; t++) {
            float xv  = __bfloat162float(xp[(size_t)t * DI]);
            float res = __bfloat162float(rp[(size_t)t * (2 * DI)]);
            float yl  = __bfloat162float(yp[(size_t)t * DI]);
            float sres = res / (1.f + __expf(-res));
            yp[(size_t)t * DI] = __float2bfloat16((yl + Dv * xv) * sres);
        }
        return;
    }

    __shared__ float sX[CH][XDBLC];
    for (int i = tid; i < CH * 12; i += 128) {
        int tt = i / 12, q = i % 12;
        *(float4*)&sX[tt][q * 4] =
            *(const float4*)&xdbl[(size_t)(base + tt) * XDBLC + q * 4];
    }
    __syncthreads();

    // combine: incoming state w for this chunk from prior chunks' (hfin, dS)
    float w[16];
    #pragma unroll
    for (int n = 0; n < 16; n++) w[n] = 0.f;
    for (int c = 0; c < ch; c++) {
        size_t cc = (size_t)(zb * NCH + c);
        float S = dSb[cc * 512 + d];
        float P[16];
        if (fast) {
            powers16(__expf(S * a1), P);
        } else {
            #pragma unroll
            for (int n = 0; n < 16; n++) P[n] = __expf(S * a[n]);
        }
        #pragma unroll
        for (int n = 0; n < 16; n++)
            w[n] = fmaf(P[n], w[n], hfin[cc * 8192 + n * 512 + d]);
    }

    float wreg[16];
    #pragma unroll
    for (int j = 0; j < 16; j++) wreg[j] = dtW[j * DI + d];
    float dbias = dtB[d];

    if (fast) {
        float r = 1.f;
        #pragma unroll 2
        for (int t = 0; t < CH; t++) {
            float raw = dbias;
            #pragma unroll
            for (int j = 0; j < 16; j++) raw = fmaf(wreg[j], sX[t][j], raw);
            float dlt = softplus_f(raw);
            float xv  = __bfloat162float(xp[(size_t)t * DI]);
            float res = __bfloat162float(rp[(size_t)t * (2 * DI)]);
            float yl  = __bfloat162float(yp[(size_t)t * DI]);
            r *= __expf(dlt * a1);
            float p[16];
            powers16(r, p);
            float corr = 0.f;
            #pragma unroll
            for (int n = 0; n < 16; n++)
                corr = fmaf(w[n] * p[n], sX[t][32 + n], corr);
            float sres = res / (1.f + __expf(-res));
            yp[(size_t)t * DI] = __float2bfloat16((yl + corr + Dv * xv) * sres);
        }
    } else {
        float S = 0.f;
        for (int t = 0; t < CH; t++) {
            float raw = dbias;
            #pragma unroll
            for (int j = 0; j < 16; j++) raw = fmaf(wreg[j], sX[t][j], raw);
            float dlt = softplus_f(raw);
            float xv  = __bfloat162float(xp[(size_t)t * DI]);
            float res = __bfloat162float(rp[(size_t)t * (2 * DI)]);
            float yl  = __bfloat162float(yp[(size_t)t * DI]);
            S += dlt;
            float corr = 0.f;
            #pragma unroll
            for (int n = 0; n < 16; n++)
                corr = fmaf(w[n] * __expf(S * a[n]), sX[t][32 + n], corr);
            float sres = res / (1.f + __expf(-res));
            yp[(size_t)t * DI] = __float2bfloat16((yl + corr + Dv * xv) * sres);
        }
    }
}

// ---------------- launcher -------------------------------------------------
extern "C" void kernel_launch(void* const* d_in, const int* in_sizes, int n_in,
                              void* d_out, int out_size)
{
    const float* x      = (const float*)d_in[0];
    const float* norm_g = (const float*)d_in[1];
    const float* norm_b = (const float*)d_in[2];
    const float* inW[2]   = {(const float*)d_in[3],  (const float*)d_in[12]};
    const float* convW[2] = {(const float*)d_in[4],  (const float*)d_in[13]};
    const float* convB[2] = {(const float*)d_in[5],  (const float*)d_in[14]};
    const float* xW[2]    = {(const float*)d_in[6],  (const float*)d_in[15]};
    const float* dtW[2]   = {(const float*)d_in[7],  (const float*)d_in[16]};
    const float* dtB[2]   = {(const float*)d_in[8],  (const float*)d_in[17]};
    const float* ALog[2]  = {(const float*)d_in[9],  (const float*)d_in[18]};
    const float* Dp[2]    = {(const float*)d_in[10], (const float*)d_in[19]};
    const float* outW[2]  = {(const float*)d_in[11], (const float*)d_in[20]};
    const float* fusW = (const float*)d_in[21];
    const float* fusB = (const float*)d_in[22];
    float* out = (float*)d_out;

    float* base = nullptr;
    cudaGetSymbolAddress((void**)&base, g_buf);
    BF*    xn_h      = (BF*)(base + OFF_XNH);
    BF*    xr_[2]    = {(BF*)(base + OFF_XRH),  (BF*)(base + OFF_XRH)  + (size_t)BL * 2 * DI};
    BF*    xsch_[2]  = {(BF*)(base + OFF_XSCH), (BF*)(base + OFF_XSCH) + (size_t)BL * DI};
    float* xdbl_[2]  = {base + OFF_XDBL, base + OFF_XDBL + (size_t)BL * XDBLC};
    BF*    yb_[2]    = {(BF*)(base + OFF_YB),   (BF*)(base + OFF_YB)   + (size_t)BL * DI};
    BF*    WtIn[2]   = {(BF*)(base + OFF_WTIN), (BF*)(base + OFF_WTIN) + (size_t)1024 * 256};
    BF*    WtX[2]    = {(BF*)(base + OFF_WTX),  (BF*)(base + OFF_WTX)  + (size_t)48 * 512};
    BF*    fusWt     = (BF*)(base + OFF_FWT);
    BF*    outWh[2]  = {(BF*)(base + OFF_OWH),  (BF*)(base + OFF_OWH)  + (size_t)512 * 256};
    BF*    WcombT    = (BF*)(base + OFF_WCT);
    float* hfin      = base + OFF_HF;
    float* dSb       = base + OFF_DS;

    static bool attr_set = false;
    if (!attr_set) {
        cudaFuncSetAttribute(mma_gemm, cudaFuncAttributeMaxDynamicSharedMemorySize, SMEM_BYTES);
        attr_set = true;
    }

    // 1) fused prep: weight transforms + LayerNorm
    prep_kernel<<<1984, 256>>>(inW[0], inW[1], xW[0], xW[1], fusW, outW[0], outW[1],
                               WtIn[0], WtIn[1], WtX[0], WtX[1], fusWt, outWh[0], outWh[1],
                               x, norm_g, norm_b, xn_h);

    // 2) WcombT[n, k + z*512] = sum_j fusWt[n, z*256+j] * outWh_z[k, j]
    mma_gemm<<<dim3(2, 4, 2), 256, SMEM_BYTES>>>(
        fusWt, fusWt + 256, 512, 0,
        outWh[0], outWh[1], 256,
        (float*)WcombT, (float*)WcombT, 1024, 512,
        512, 256, 3, nullptr, nullptr, nullptr);

    // 3) in_proj -> bf16 xr, both dirs (flip A rows for backward)
    mma_gemm<<<dim3(BL / 128, 8, 2), 256, SMEM_BYTES>>>(
        xn_h, xn_h, DM, 1,
        WtIn[0], WtIn[1], 256,
        (float*)xr_[0], (float*)xr_[1], 2 * DI, 0,
        2 * DI, DM, 3, nullptr, nullptr, nullptr);

    // 4) causal dw-conv + silu -> bf16 xsc
    conv_silu_kernel<<<dim3((BL / 4) * DI / 256, 2), 256>>>(
        xr_[0], xr_[1], convW[0], convW[1], convB[0], convB[1],
        xsch_[0], xsch_[1]);

    // 5) x_proj -> [dlt | B | C] (f32)
    mma_gemm<<<dim3(BL / 128, 1, 2), 256, SMEM_BYTES>>>(
        xsch_[0], xsch_[1], DI, 0,
        WtX[0], WtX[1], 512,
        xdbl_[0], xdbl_[1], XDBLC, 0,
        XDBLC, DI, 0, nullptr, nullptr, nullptr);

    // 6) chunked scan: local (A) -> combine+correct+gate (C)
    scanA_kernel<<<dim3(DI / 128, NCH, 16), 128>>>(
        xdbl_[0], xdbl_[1], xsch_[0], xsch_[1],
        dtW[0], dtW[1], dtB[0], dtB[1],
        ALog[0], ALog[1], yb_[0], yb_[1], hfin, dSb);
    scanC_kernel<<<dim3(DI / 128, NCH, 16), 128>>>(
        xdbl_[0], xdbl_[1], xsch_[0], xsch_[1], xr_[0], xr_[1],
        dtW[0], dtW[1], dtB[0], dtB[1],
        ALog[0], ALog[1], Dp[0], Dp[1], yb_[0], yb_[1], hfin, dSb);

    // 7) combined out_proj + fuse + residual (dual-A, K=1024)
    mma_gemm<<<dim3(BL / 128, 2, 1), 256, SMEM_BYTES>>>(
        yb_[0], yb_[1], DI, 2,
        WcombT, WcombT, 1024,
        out, out, DM, 0,
        DM, 1024, 2, fusB, fusB, x);
}